// round 4
// baseline (speedup 1.0000x reference)
#include <cuda_runtime.h>
#include <math.h>

#define Bb 32
#define Ss 256
#define Vv 10000
#define Ee 512
#define Hh 1024
#define Ll 3

// ---------------- scratch (static __device__ arrays; no allocation) ----------------
__device__ float g_fp[Bb * Ss];                  // layer-normed fix_pred, [B,S]
__device__ float g_inputx[Ss * Bb * Hh];         // input projection, [S,B,H]
__device__ float g_inp[Ss * Bb * Hh];            // gated layer input,  [S,B,H]
__device__ float g_x[Ss * Bb * Hh];              // layer output / h history, [S,B,H]
__device__ float g_gin[Ss * Bb * 4 * Hh];        // precomputed input gates, [S,B,4H]
__device__ float g_wht[Hh * 4 * Hh];             // W_hh[l] transposed -> [K=1024, N=4096]
__device__ float g_c[Bb * Hh];                   // cell state
__device__ float g_hid[Bb * Ss * Ee];            // fc1 output, [B,S,E]

__device__ __forceinline__ float sigmoidf_(float x) { return 1.0f / (1.0f + expf(-x)); }

// ---- packed f32x2 helpers (Blackwell FFMA2 path, PTX-only) ----
__device__ __forceinline__ unsigned long long splat2(float x) {
    unsigned long long r;
    asm("mov.b64 %0, {%1, %1};" : "=l"(r) : "f"(x));
    return r;
}
__device__ __forceinline__ unsigned long long pack2(float x, float y) {
    unsigned long long r;
    asm("mov.b64 %0, {%1, %2};" : "=l"(r) : "f"(x), "f"(y));
    return r;
}
__device__ __forceinline__ float2 unpack2(unsigned long long v) {
    float2 r;
    asm("mov.b64 {%0, %1}, %2;" : "=f"(r.x), "=f"(r.y) : "l"(v));
    return r;
}
__device__ __forceinline__ void fma2(unsigned long long& d,
                                     unsigned long long a, unsigned long long b) {
    asm("fma.rn.f32x2 %0, %1, %2, %0;" : "+l"(d) : "l"(a), "l"(b));
}

// ---------------- layer norm over seq dim ----------------
__global__ void ln_kernel(const float* __restrict__ fixp, float* __restrict__ fp) {
    __shared__ float red[256];
    int b = blockIdx.x, s = threadIdx.x;
    float v = fixp[b * Ss + s];
    red[s] = v;
    __syncthreads();
    for (int o = 128; o > 0; o >>= 1) { if (s < o) red[s] += red[s + o]; __syncthreads(); }
    float mu = red[0] * (1.0f / Ss);
    __syncthreads();
    float d = v - mu;
    red[s] = d * d;
    __syncthreads();
    for (int o = 128; o > 0; o >>= 1) { if (s < o) red[s] += red[s + o]; __syncthreads(); }
    float var = red[0] * (1.0f / Ss);
    float y = d * rsqrtf(var + 1e-5f);
    fp[b * Ss + s] = (y + 1.96f) / 3.92f * 12.0f;
}

// ---------------- W_hh transpose: [4H,H] -> [H,4H] ----------------
__global__ void transpose_kernel(const float* __restrict__ in, float* __restrict__ out) {
    __shared__ float t[32][33];
    int n0 = blockIdx.x * 32, k0 = blockIdx.y * 32;
    int tx = threadIdx.x, ty = threadIdx.y;
    t[ty][tx] = in[(n0 + ty) * Hh + (k0 + tx)];
    __syncthreads();
    out[(size_t)(k0 + ty) * (4 * Hh) + (n0 + tx)] = t[tx][ty];
}

// ---------------- gated input blend ----------------
__global__ void ew_kernel(const float* __restrict__ x, const float* __restrict__ ix,
                          const float* __restrict__ fp, float* __restrict__ inp, int layer) {
    int idx = blockIdx.x * 256 + threadIdx.x;
    int sb = idx >> 10;
    int b = sb & 31;
    int s = sb >> 5;
    float alpha = (11.0f - fp[b * Ss + s]) * 0.25f - (float)layer;
    float mask = sigmoidf_(alpha);
    float gate = sigmoidf_(alpha + 1.0f) - mask;
    float xv = (layer == 0) ? 0.0f : x[idx];
    inp[idx] = xv * (1.0f - gate) + ix[idx] * gate;
}

// ---------------- generic SGEMM: C[M,N] = A_gathered[M,K] * B[N,K]^T (+bias, act) ----
// Double-buffered smem, BK=16, single __syncthreads per k-tile.
// MODE 0: A row = m
// MODE 1: A = emb, row = src[b*S+s] with m = s*B+b   (input projection)
// MODE 2: A = x [S,B,H], logical row m = b*S+s reads physical row s*B+b  (fc1 reorder)
// ACT  1: tanh epilogue
template <int MODE, int ACT>
__global__ void __launch_bounds__(256) sgemm_kernel(
    const float* __restrict__ A, const float* __restrict__ Bm, float* __restrict__ C,
    const float* __restrict__ bias1, const float* __restrict__ bias2,
    int M, int N, int K, const int* __restrict__ src)
{
    __shared__ float As[2][16][128];
    __shared__ float Bs[2][16][128];
    int tid = threadIdx.x;
    int m0 = blockIdx.y * 128, n0 = blockIdx.x * 128;

    int lr = tid >> 1;            // 0..127 (tile row for loads)
    int kq = (tid & 1) * 8;       // 0 or 8; this thread covers k [kq, kq+8)

    int am = m0 + lr;
    long arow;
    if (MODE == 1)      { int b = am & 31;  int s = am >> 5; arow = src[b * Ss + s]; }
    else if (MODE == 2) { int s = am & 255; int b = am >> 8; arow = (long)s * Bb + b; }
    else                { arow = am; }
    const float* aptr = A + arow * (long)K + kq;

    int bn = n0 + lr;
    bool bok = (bn < N);
    const float* bptr = Bm + (long)bn * K + kq;

    int tx = tid & 15, ty = tid >> 4;

    // packed accumulators: acc[i][jp] = f32x2 pair of output cols
    unsigned long long acc[8][4];
#pragma unroll
    for (int i = 0; i < 8; i++)
#pragma unroll
        for (int j = 0; j < 4; j++) acc[i][j] = 0ULL;

    int T = K / 16;

    // prefetch tile 0 and store to buffer 0
    float4 aR0 = *(const float4*)(aptr);
    float4 aR1 = *(const float4*)(aptr + 4);
    float4 bR0 = bok ? *(const float4*)(bptr)     : make_float4(0.f, 0.f, 0.f, 0.f);
    float4 bR1 = bok ? *(const float4*)(bptr + 4) : make_float4(0.f, 0.f, 0.f, 0.f);
    As[0][kq + 0][lr] = aR0.x; As[0][kq + 1][lr] = aR0.y; As[0][kq + 2][lr] = aR0.z; As[0][kq + 3][lr] = aR0.w;
    As[0][kq + 4][lr] = aR1.x; As[0][kq + 5][lr] = aR1.y; As[0][kq + 6][lr] = aR1.z; As[0][kq + 7][lr] = aR1.w;
    Bs[0][kq + 0][lr] = bR0.x; Bs[0][kq + 1][lr] = bR0.y; Bs[0][kq + 2][lr] = bR0.z; Bs[0][kq + 3][lr] = bR0.w;
    Bs[0][kq + 4][lr] = bR1.x; Bs[0][kq + 5][lr] = bR1.y; Bs[0][kq + 6][lr] = bR1.z; Bs[0][kq + 7][lr] = bR1.w;
    __syncthreads();

    for (int t = 0; t < T; t++) {
        int cur = t & 1, nxt = cur ^ 1;
        if (t + 1 < T) {
            const float* ap = aptr + (t + 1) * 16;
            const float* bp = bptr + (t + 1) * 16;
            aR0 = *(const float4*)(ap);
            aR1 = *(const float4*)(ap + 4);
            bR0 = bok ? *(const float4*)(bp)     : make_float4(0.f, 0.f, 0.f, 0.f);
            bR1 = bok ? *(const float4*)(bp + 4) : make_float4(0.f, 0.f, 0.f, 0.f);
        }
#pragma unroll
        for (int k = 0; k < 16; k++) {
            float4 a0 = *(const float4*)&As[cur][k][ty * 4];
            float4 a1 = *(const float4*)&As[cur][k][64 + ty * 4];
            ulonglong2 bp01 = *(const ulonglong2*)&Bs[cur][k][tx * 4];
            ulonglong2 bp23 = *(const ulonglong2*)&Bs[cur][k][64 + tx * 4];
            unsigned long long aa[8];
            aa[0] = splat2(a0.x); aa[1] = splat2(a0.y); aa[2] = splat2(a0.z); aa[3] = splat2(a0.w);
            aa[4] = splat2(a1.x); aa[5] = splat2(a1.y); aa[6] = splat2(a1.z); aa[7] = splat2(a1.w);
#pragma unroll
            for (int i = 0; i < 8; i++) {
                fma2(acc[i][0], aa[i], bp01.x);
                fma2(acc[i][1], aa[i], bp01.y);
                fma2(acc[i][2], aa[i], bp23.x);
                fma2(acc[i][3], aa[i], bp23.y);
            }
        }
        if (t + 1 < T) {
            As[nxt][kq + 0][lr] = aR0.x; As[nxt][kq + 1][lr] = aR0.y; As[nxt][kq + 2][lr] = aR0.z; As[nxt][kq + 3][lr] = aR0.w;
            As[nxt][kq + 4][lr] = aR1.x; As[nxt][kq + 5][lr] = aR1.y; As[nxt][kq + 6][lr] = aR1.z; As[nxt][kq + 7][lr] = aR1.w;
            Bs[nxt][kq + 0][lr] = bR0.x; Bs[nxt][kq + 1][lr] = bR0.y; Bs[nxt][kq + 2][lr] = bR0.z; Bs[nxt][kq + 3][lr] = bR0.w;
            Bs[nxt][kq + 4][lr] = bR1.x; Bs[nxt][kq + 5][lr] = bR1.y; Bs[nxt][kq + 6][lr] = bR1.z; Bs[nxt][kq + 7][lr] = bR1.w;
        }
        __syncthreads();
    }

#pragma unroll
    for (int i = 0; i < 8; i++) {
        int row = m0 + ((i < 4) ? (ty * 4 + i) : (64 + ty * 4 + (i - 4)));
#pragma unroll
        for (int jh = 0; jh < 2; jh++) {
            int col = n0 + (jh ? (64 + tx * 4) : (tx * 4));
            if (col < N) {
                float2 p0 = unpack2(acc[i][jh * 2 + 0]);
                float2 p1 = unpack2(acc[i][jh * 2 + 1]);
                float v0 = p0.x, v1 = p0.y, v2 = p1.x, v3 = p1.y;
                if (bias1) { v0 += bias1[col]; v1 += bias1[col + 1]; v2 += bias1[col + 2]; v3 += bias1[col + 3]; }
                if (bias2) { v0 += bias2[col]; v1 += bias2[col + 1]; v2 += bias2[col + 2]; v3 += bias2[col + 3]; }
                if (ACT == 1) { v0 = tanhf(v0); v1 = tanhf(v1); v2 = tanhf(v2); v3 = tanhf(v3); }
                float4 v; v.x = v0; v.y = v1; v.z = v2; v.w = v3;
                *(float4*)(&C[(long)row * N + col]) = v;
            }
        }
    }
}

// ---------------- one LSTM time step ----------------
// grid 128 CTAs (8 hidden units each, all 32 batches), 256 threads = 32 b x 8 jj.
// h for this step is x[s-1] (or h0 at s==0); Wh is pre-transposed [K,4H].
// W chunks double-buffered: stage kc+1 (4x LDG.128/thread) while computing kc.
#define HPAD 1028  /* words; mult of 4 for float4 */
#define WCH  (128 * 32)  /* floats per W chunk */
#define STEP_SMEM ((32 * HPAD + 2 * WCH) * 4)

__global__ void __launch_bounds__(256) lstm_step_kernel(
    const float* __restrict__ gin,   // [S,B,4H]
    const float* __restrict__ wht,   // [1024,4096]
    const float* __restrict__ fp,    // [B,S]
    const float* __restrict__ h0l,   // [B,H] (layer slice)
    const float* __restrict__ c0l,   // [B,H]
    float* __restrict__ x,           // [S,B,H]
    float* __restrict__ cst,         // [B,H]
    int s, int layer)
{
    extern __shared__ float sm[];
    float* hsm = sm;                 // [32][HPAD]
    float* wsm = sm + 32 * HPAD;     // [2][128][32] = [buf][kk][jj*4 + gate]

    int tid = threadIdx.x;
    int j0 = blockIdx.x * 8;
    const float* hsrc = (s == 0) ? h0l : (x + (long)(s - 1) * Bb * Hh);

    // W staging decomposition (per thread: 4 float4 per chunk)
    // f = tid*4 + i  in [0,1024): kk = f>>3, gate = (f&7)>>1, half = f&1
    int f0 = tid * 4;
    int w_kk[4], w_gate[4], w_half[4];
#pragma unroll
    for (int i = 0; i < 4; i++) {
        int f = f0 + i;
        w_kk[i] = f >> 3; w_gate[i] = (f & 7) >> 1; w_half[i] = f & 1;
    }

    // stage W chunk 0 (prefetch to regs, then STS)
    float4 wv[4];
#pragma unroll
    for (int i = 0; i < 4; i++)
        wv[i] = *(const float4*)(wht + (long)w_kk[i] * 4096 + w_gate[i] * 1024 + j0 + w_half[i] * 4);

    // stage full h (128 KB) into smem
    for (int i = tid; i < (Bb * Hh) / 4; i += 256) {
        float4 v = *(const float4*)(hsrc + i * 4);
        int b = (i * 4) >> 10;
        int k = (i * 4) & 1023;
        *(float4*)(hsm + b * HPAD + k) = v;
    }

#pragma unroll
    for (int i = 0; i < 4; i++) {
        float* d = wsm + w_kk[i] * 32 + w_half[i] * 16 + w_gate[i];
        d[0] = wv[i].x; d[4] = wv[i].y; d[8] = wv[i].z; d[12] = wv[i].w;
    }

    int b = tid >> 3, jj = tid & 7;
    int j = j0 + jj;

    // packed accumulators: accA = (i, f) gates, accB = (g, o) gates
    unsigned long long accA, accB;
    {
        long gbase = ((long)(s * Bb + b)) * 4096 + j;
        accA = pack2(gin[gbase],        gin[gbase + 1024]);
        accB = pack2(gin[gbase + 2048], gin[gbase + 3072]);
    }
    __syncthreads();

    for (int kc = 0; kc < 8; kc++) {
        int cur = kc & 1, nxt = cur ^ 1;
        if (kc + 1 < 8) {
            const float* wbase = wht + (long)(kc + 1) * 128 * 4096;
#pragma unroll
            for (int i = 0; i < 4; i++)
                wv[i] = *(const float4*)(wbase + (long)w_kk[i] * 4096 + w_gate[i] * 1024 + j0 + w_half[i] * 4);
        }
        const float* hrow = hsm + b * HPAD + kc * 128;
        const float* wcur = wsm + cur * WCH;
#pragma unroll 8
        for (int k4 = 0; k4 < 32; k4++) {
            float4 hv = *(const float4*)(hrow + k4 * 4);
            const unsigned long long* wb =
                (const unsigned long long*)(wcur + (k4 * 4) * 32 + jj * 4);
            unsigned long long ha;
            ha = splat2(hv.x);
            fma2(accA, ha, wb[0]);  fma2(accB, ha, wb[1]);
            ha = splat2(hv.y);
            fma2(accA, ha, wb[16]); fma2(accB, ha, wb[17]);
            ha = splat2(hv.z);
            fma2(accA, ha, wb[32]); fma2(accB, ha, wb[33]);
            ha = splat2(hv.w);
            fma2(accA, ha, wb[48]); fma2(accB, ha, wb[49]);
        }
        if (kc + 1 < 8) {
            float* wdst = wsm + nxt * WCH;
#pragma unroll
            for (int i = 0; i < 4; i++) {
                float* d = wdst + w_kk[i] * 32 + w_half[i] * 16 + w_gate[i];
                d[0] = wv[i].x; d[4] = wv[i].y; d[8] = wv[i].z; d[12] = wv[i].w;
            }
        }
        __syncthreads();
    }

    float2 pA = unpack2(accA);
    float2 pB = unpack2(accB);
    float i_ = sigmoidf_(pA.x);
    float f_ = sigmoidf_(pA.y);
    float g_ = tanhf(pB.x);
    float o_ = sigmoidf_(pB.y);
    float c_old = (s == 0) ? c0l[b * Hh + j] : cst[b * Hh + j];
    float h_old = hsm[b * HPAD + j];
    float cn = f_ * c_old + i_ * g_;
    float hn = o_ * tanhf(cn);
    float m = sigmoidf_((11.0f - fp[b * Ss + s]) * 0.25f - (float)layer);
    cn = cn * (1.0f - m) + c_old * m;
    hn = hn * (1.0f - m) + h_old * m;
    cst[b * Hh + j] = cn;
    x[((long)(s * Bb + b)) * Hh + j] = hn;
}

// ---------------- launch ----------------
extern "C" void kernel_launch(void* const* d_in, const int* in_sizes, int n_in,
                              void* d_out, int out_size) {
    (void)in_sizes; (void)n_in; (void)out_size;
    const int*   src   = (const int*)  d_in[0];
    const float* fixp  = (const float*)d_in[1];
    const float* emb   = (const float*)d_in[2];
    const float* W_lin = (const float*)d_in[3];
    const float* b_lin = (const float*)d_in[4];
    const float* W_ih  = (const float*)d_in[5];
    const float* W_hh  = (const float*)d_in[6];
    const float* b_ih  = (const float*)d_in[7];
    const float* b_hh  = (const float*)d_in[8];
    const float* fc_W1 = (const float*)d_in[9];
    const float* fc_b1 = (const float*)d_in[10];
    const float* fc_W2 = (const float*)d_in[11];
    const float* fc_b2 = (const float*)d_in[12];
    const float* h0    = (const float*)d_in[13];
    const float* c0    = (const float*)d_in[14];
    float* out = (float*)d_out;

    float *fp, *inputx, *inp, *x, *gin, *wht, *cst, *hid;
    cudaGetSymbolAddress((void**)&fp,     g_fp);
    cudaGetSymbolAddress((void**)&inputx, g_inputx);
    cudaGetSymbolAddress((void**)&inp,    g_inp);
    cudaGetSymbolAddress((void**)&x,      g_x);
    cudaGetSymbolAddress((void**)&gin,    g_gin);
    cudaGetSymbolAddress((void**)&wht,    g_wht);
    cudaGetSymbolAddress((void**)&cst,    g_c);
    cudaGetSymbolAddress((void**)&hid,    g_hid);

    cudaFuncSetAttribute(lstm_step_kernel,
                         cudaFuncAttributeMaxDynamicSharedMemorySize, STEP_SMEM);

    // 1) layer norm of fix_pred
    ln_kernel<<<Bb, 256>>>(fixp, fp);

    // 2) input projection: input_x[s,b,:] = W_lin @ emb[src[b,s],:] + b_lin
    sgemm_kernel<1, 0><<<dim3(Hh / 128, (Ss * Bb) / 128), 256>>>(
        emb, W_lin, inputx, b_lin, nullptr, Ss * Bb, Hh, Ee, src);

    // 3) three LSTM layers
    for (int l = 0; l < Ll; l++) {
        transpose_kernel<<<dim3(4 * Hh / 32, Hh / 32), dim3(32, 32)>>>(
            W_hh + (long)l * 4 * Hh * Hh, wht);
        ew_kernel<<<(Ss * Bb * Hh) / 256, 256>>>(x, inputx, fp, inp, l);
        sgemm_kernel<0, 0><<<dim3(4 * Hh / 128, (Ss * Bb) / 128), 256>>>(
            inp, W_ih + (long)l * 4 * Hh * Hh, gin,
            b_ih + (long)l * 4 * Hh, b_hh + (long)l * 4 * Hh,
            Ss * Bb, 4 * Hh, Hh, nullptr);
        for (int s = 0; s < Ss; s++) {
            lstm_step_kernel<<<128, 256, STEP_SMEM>>>(
                gin, wht, fp, h0 + (long)l * Bb * Hh, c0 + (long)l * Bb * Hh,
                x, cst, s, l);
        }
    }

    // 4) fc1 with tanh (reorders [S,B,H] -> [B,S,E])
    sgemm_kernel<2, 1><<<dim3(Ee / 128, (Ss * Bb) / 128), 256>>>(
        x, fc_W1, hid, fc_b1, nullptr, Ss * Bb, Ee, Hh, nullptr);

    // 5) fc2 -> logits [B,S,V]
    sgemm_kernel<0, 0><<<dim3((Vv + 127) / 128, (Ss * Bb) / 128), 256>>>(
        hid, fc_W2, out, fc_b2, nullptr, Ss * Bb, Vv, Ee, nullptr);
}

// round 7
// speedup vs baseline: 1.3241x; 1.3241x over previous
#include <cuda_runtime.h>
#include <cuda_bf16.h>
#include <math.h>
#include <stdint.h>

#define Bb 32
#define Ss 256
#define Vv 10000
#define Ee 512
#define Hh 1024
#define Ll 3

#define NPAD_FC2 10112   /* 79 * 128 */

// ---------------- scratch (static __device__ arrays; no allocation) ----------------
__device__ float g_fp[Bb * Ss];
__device__ float g_inputx[Ss * Bb * Hh];
__device__ float g_inp[Ss * Bb * Hh];
__device__ float g_x[Ss * Bb * Hh];
__device__ float g_gin[Ss * Bb * 4 * Hh];
__device__ float g_wht[Hh * 4 * Hh];
__device__ float g_c[Bb * Hh];
__device__ float g_hid[Bb * Ss * Ee];
// bf16 split scratch
__device__ __nv_bfloat16 g_ahi[Ss * Bb * Hh];
__device__ __nv_bfloat16 g_alo[Ss * Bb * Hh];
__device__ __nv_bfloat16 g_bhi[NPAD_FC2 * Ee > 4 * Hh * Hh ? NPAD_FC2 * Ee : 4 * Hh * Hh];
__device__ __nv_bfloat16 g_blo[NPAD_FC2 * Ee > 4 * Hh * Hh ? NPAD_FC2 * Ee : 4 * Hh * Hh];

__device__ __forceinline__ float sigmoidf_(float x) { return 1.0f / (1.0f + expf(-x)); }

// ---- packed f32x2 helpers ----
__device__ __forceinline__ unsigned long long splat2(float x) {
    unsigned long long r; asm("mov.b64 %0, {%1, %1};" : "=l"(r) : "f"(x)); return r;
}
__device__ __forceinline__ unsigned long long pack2(float x, float y) {
    unsigned long long r; asm("mov.b64 %0, {%1, %2};" : "=l"(r) : "f"(x), "f"(y)); return r;
}
__device__ __forceinline__ float2 unpack2(unsigned long long v) {
    float2 r; asm("mov.b64 {%0, %1}, %2;" : "=f"(r.x), "=f"(r.y) : "l"(v)); return r;
}
__device__ __forceinline__ void fma2(unsigned long long& d,
                                     unsigned long long a, unsigned long long b) {
    asm("fma.rn.f32x2 %0, %1, %2, %0;" : "+l"(d) : "l"(a), "l"(b));
}

__device__ __forceinline__ uint32_t smem_to_u32(const void* p) {
    uint32_t a;
    asm("{ .reg .u64 t; cvta.to.shared.u64 t, %1; cvt.u32.u64 %0, t; }" : "=r"(a) : "l"(p));
    return a;
}

// ---- warp-level tensor core (baseline PTX, works on target sm_103) ----
__device__ __forceinline__ void ldsm4(uint32_t& r0, uint32_t& r1, uint32_t& r2, uint32_t& r3,
                                      uint32_t addr) {
    asm volatile("ldmatrix.sync.aligned.m8n8.x4.shared.b16 {%0,%1,%2,%3}, [%4];"
                 : "=r"(r0), "=r"(r1), "=r"(r2), "=r"(r3) : "r"(addr));
}
__device__ __forceinline__ void mma16816(float* d, const uint32_t* a, const uint32_t* b) {
    asm volatile(
        "mma.sync.aligned.m16n8k16.row.col.f32.bf16.bf16.f32 "
        "{%0,%1,%2,%3}, {%4,%5,%6,%7}, {%8,%9}, {%0,%1,%2,%3};"
        : "+f"(d[0]), "+f"(d[1]), "+f"(d[2]), "+f"(d[3])
        : "r"(a[0]), "r"(a[1]), "r"(a[2]), "r"(a[3]), "r"(b[0]), "r"(b[1]));
}

// ---------------- fp32 -> bf16 hi/lo split (with row padding) ----------------
__global__ void split_kernel(const float* __restrict__ in,
                             __nv_bfloat16* __restrict__ hi, __nv_bfloat16* __restrict__ lo,
                             int rows, int cols, int rows_pad) {
    long idx = (long)blockIdx.x * 256 + threadIdx.x;
    long n = (long)rows_pad * cols;
    if (idx >= n) return;
    long row = idx / cols;
    float v = (row < rows) ? in[idx] : 0.0f;
    __nv_bfloat16 h = __float2bfloat16_rn(v);
    float r = v - __bfloat162float(h);
    hi[idx] = h;
    lo[idx] = __float2bfloat16_rn(r);
}

// ---------------- tensor-core GEMM: C[M,Nout] = A[M,K]*B[Npad,K]^T (+biases) -------
// bf16x3: C ~= Ahi*Bhi + Ahi*Blo + Alo*Bhi, fp32 accumulate via mma.m16n8k16.
// CTA 128x128, 8 warps (warp tile 32x64), K chunk 32, reg-prefetch next chunk.
#define TCRS   80                  /* smem row stride bytes (64B data + 16B pad) */
#define TCTILE (128 * TCRS)        /* 10240 B per tile */

__global__ void __launch_bounds__(256, 1) tc_gemm_kernel(
    const __nv_bfloat16* __restrict__ ah, const __nv_bfloat16* __restrict__ al,
    const __nv_bfloat16* __restrict__ bh, const __nv_bfloat16* __restrict__ bl,
    float* __restrict__ C,
    const float* __restrict__ bias1, const float* __restrict__ bias2,
    int K, int Nout)
{
    __shared__ char smem[4 * TCTILE];   // AH | AL | BH | BL
    uint32_t sb = smem_to_u32(smem);

    int tid = threadIdx.x, lane = tid & 31, w = tid >> 5;
    int wm = w & 3, wn = w >> 2;
    int m0 = blockIdx.y * 128, n0 = blockIdx.x * 128;

    // ---- staging geometry: thread stages one 32B segment per tile per chunk ----
    int srow = tid >> 1;               // 0..127
    int sun  = (tid & 1) * 2;          // 16B-unit 0 or 2
    long gofs = (long)srow * K + sun * 8;
    const __nv_bfloat16* gAh = ah + (long)(m0 + srow) * K + sun * 8;
    const __nv_bfloat16* gAl = al + (long)(m0 + srow) * K + sun * 8;
    const __nv_bfloat16* gBh = bh + (long)(n0 + srow) * K + sun * 8;
    const __nv_bfloat16* gBl = bl + (long)(n0 + srow) * K + sun * 8;
    (void)gofs;
    int sofs = srow * TCRS + sun * 16;

    // ---- ldmatrix lane addressing (row-pad 80B -> conflict-free phases) ----
    int lrow = lane & 15;
    int lcol = (lane >> 4) * 16;
    uint32_t lda = sb + (uint32_t)((wm * 32 + lrow) * TCRS + lcol);              // AH base
    uint32_t ldb = sb + 2 * TCTILE + (uint32_t)((wn * 64 + lrow) * TCRS + lcol); // BH base

    float acc[2][8][4];
#pragma unroll
    for (int mt = 0; mt < 2; mt++)
#pragma unroll
        for (int nt = 0; nt < 8; nt++)
#pragma unroll
            for (int q = 0; q < 4; q++) acc[mt][nt][q] = 0.0f;

    int NC = K / 32;
    uint4 p[8];

    // prefetch chunk 0
    p[0] = *(const uint4*)(gAh);     p[1] = *(const uint4*)(gAh + 8);
    p[2] = *(const uint4*)(gAl);     p[3] = *(const uint4*)(gAl + 8);
    p[4] = *(const uint4*)(gBh);     p[5] = *(const uint4*)(gBh + 8);
    p[6] = *(const uint4*)(gBl);     p[7] = *(const uint4*)(gBl + 8);

    for (int kc = 0; kc < NC; kc++) {
        // store staged chunk
        *(uint4*)(smem + sofs)                = p[0];
        *(uint4*)(smem + sofs + 16)           = p[1];
        *(uint4*)(smem + TCTILE + sofs)       = p[2];
        *(uint4*)(smem + TCTILE + sofs + 16)  = p[3];
        *(uint4*)(smem + 2*TCTILE + sofs)     = p[4];
        *(uint4*)(smem + 2*TCTILE + sofs + 16)= p[5];
        *(uint4*)(smem + 3*TCTILE + sofs)     = p[6];
        *(uint4*)(smem + 3*TCTILE + sofs + 16)= p[7];
        __syncthreads();

        if (kc + 1 < NC) {
            long o = (long)(kc + 1) * 32;
            p[0] = *(const uint4*)(gAh + o);     p[1] = *(const uint4*)(gAh + o + 8);
            p[2] = *(const uint4*)(gAl + o);     p[3] = *(const uint4*)(gAl + o + 8);
            p[4] = *(const uint4*)(gBh + o);     p[5] = *(const uint4*)(gBh + o + 8);
            p[6] = *(const uint4*)(gBl + o);     p[7] = *(const uint4*)(gBl + o + 8);
        }

#pragma unroll
        for (int k16 = 0; k16 < 2; k16++) {
            uint32_t AH[2][4], AL[2][4];
#pragma unroll
            for (int mt = 0; mt < 2; mt++) {
                uint32_t a0 = lda + mt * (16 * TCRS) + k16 * 32;
                ldsm4(AH[mt][0], AH[mt][1], AH[mt][2], AH[mt][3], a0);
                ldsm4(AL[mt][0], AL[mt][1], AL[mt][2], AL[mt][3], a0 + TCTILE);
            }
            uint32_t BH[8][2], BL[8][2];
#pragma unroll
            for (int np = 0; np < 4; np++) {
                uint32_t t0, t1, t2, t3;
                uint32_t b0 = ldb + np * (16 * TCRS) + k16 * 32;
                ldsm4(t0, t1, t2, t3, b0);
                BH[np*2][0] = t0; BH[np*2][1] = t2;
                BH[np*2+1][0] = t1; BH[np*2+1][1] = t3;
                ldsm4(t0, t1, t2, t3, b0 + TCTILE);
                BL[np*2][0] = t0; BL[np*2][1] = t2;
                BL[np*2+1][0] = t1; BL[np*2+1][1] = t3;
            }
            // pass 1: Ahi*Bhi (16 independent mma)
#pragma unroll
            for (int mt = 0; mt < 2; mt++)
#pragma unroll
                for (int nt = 0; nt < 8; nt++)
                    mma16816(acc[mt][nt], AH[mt], BH[nt]);
            // pass 2: Ahi*Blo
#pragma unroll
            for (int mt = 0; mt < 2; mt++)
#pragma unroll
                for (int nt = 0; nt < 8; nt++)
                    mma16816(acc[mt][nt], AH[mt], BL[nt]);
            // pass 3: Alo*Bhi
#pragma unroll
            for (int mt = 0; mt < 2; mt++)
#pragma unroll
                for (int nt = 0; nt < 8; nt++)
                    mma16816(acc[mt][nt], AL[mt], BH[nt]);
        }
        __syncthreads();
    }

    // ---- epilogue: d0/d1 -> (row g, col c..c+1), d2/d3 -> (row g+8) ----
    int g = lane >> 2, tq = lane & 3;
#pragma unroll
    for (int mt = 0; mt < 2; mt++) {
        int row0 = m0 + wm * 32 + mt * 16 + g;
#pragma unroll
        for (int nt = 0; nt < 8; nt++) {
            int col = n0 + wn * 64 + nt * 8 + tq * 2;
            if (col < Nout) {
                float b1v0 = bias1 ? bias1[col]     : 0.0f;
                float b1v1 = bias1 ? bias1[col + 1] : 0.0f;
                if (bias2) { b1v0 += bias2[col]; b1v1 += bias2[col + 1]; }
                float2 v01; v01.x = acc[mt][nt][0] + b1v0; v01.y = acc[mt][nt][1] + b1v1;
                float2 v23; v23.x = acc[mt][nt][2] + b1v0; v23.y = acc[mt][nt][3] + b1v1;
                *(float2*)(&C[(long)row0 * Nout + col]) = v01;
                *(float2*)(&C[(long)(row0 + 8) * Nout + col]) = v23;
            }
        }
    }
}

// ---------------- layer norm over seq dim ----------------
__global__ void ln_kernel(const float* __restrict__ fixp, float* __restrict__ fp) {
    __shared__ float red[256];
    int b = blockIdx.x, s = threadIdx.x;
    float v = fixp[b * Ss + s];
    red[s] = v;
    __syncthreads();
    for (int o = 128; o > 0; o >>= 1) { if (s < o) red[s] += red[s + o]; __syncthreads(); }
    float mu = red[0] * (1.0f / Ss);
    __syncthreads();
    float d = v - mu;
    red[s] = d * d;
    __syncthreads();
    for (int o = 128; o > 0; o >>= 1) { if (s < o) red[s] += red[s + o]; __syncthreads(); }
    float var = red[0] * (1.0f / Ss);
    float y = d * rsqrtf(var + 1e-5f);
    fp[b * Ss + s] = (y + 1.96f) / 3.92f * 12.0f;
}

// ---------------- W_hh transpose: [4H,H] -> [H,4H] ----------------
__global__ void transpose_kernel(const float* __restrict__ in, float* __restrict__ out) {
    __shared__ float t[32][33];
    int n0 = blockIdx.x * 32, k0 = blockIdx.y * 32;
    int tx = threadIdx.x, ty = threadIdx.y;
    t[ty][tx] = in[(n0 + ty) * Hh + (k0 + tx)];
    __syncthreads();
    out[(size_t)(k0 + ty) * (4 * Hh) + (n0 + tx)] = t[tx][ty];
}

// ---------------- gated input blend ----------------
__global__ void ew_kernel(const float* __restrict__ x, const float* __restrict__ ix,
                          const float* __restrict__ fp, float* __restrict__ inp, int layer) {
    int idx = blockIdx.x * 256 + threadIdx.x;
    int sb = idx >> 10;
    int b = sb & 31;
    int s = sb >> 5;
    float alpha = (11.0f - fp[b * Ss + s]) * 0.25f - (float)layer;
    float mask = sigmoidf_(alpha);
    float gate = sigmoidf_(alpha + 1.0f) - mask;
    float xv = (layer == 0) ? 0.0f : x[idx];
    inp[idx] = xv * (1.0f - gate) + ix[idx] * gate;
}

// ---------------- SGEMM (R3 version) for small GEMMs ----------------
template <int MODE, int ACT>
__global__ void __launch_bounds__(256) sgemm_kernel(
    const float* __restrict__ A, const float* __restrict__ Bm, float* __restrict__ C,
    const float* __restrict__ bias1, const float* __restrict__ bias2,
    int M, int N, int K, const int* __restrict__ src)
{
    __shared__ float As[8][128];
    __shared__ float Bs[8][128];
    int tid = threadIdx.x;
    int m0 = blockIdx.y * 128, n0 = blockIdx.x * 128;

    int lr = tid >> 1;
    int kq = (tid & 1) * 4;

    int am = m0 + lr;
    long arow;
    if (MODE == 1)      { int b = am & 31;  int s = am >> 5; arow = src[b * Ss + s]; }
    else if (MODE == 2) { int s = am & 255; int b = am >> 8; arow = (long)s * Bb + b; }
    else                { arow = am; }
    const float* aptr = A + arow * (long)K + kq;

    int bn = n0 + lr;
    bool bok = (bn < N);
    const float* bptr = Bm + (long)bn * K + kq;

    int tx = tid & 15, ty = tid >> 4;

    unsigned long long acc[8][4];
#pragma unroll
    for (int i = 0; i < 8; i++)
#pragma unroll
        for (int j = 0; j < 4; j++) acc[i][j] = 0ULL;

    int T = K / 8;
    float4 aR = *(const float4*)(aptr);
    float4 bR = bok ? *(const float4*)(bptr) : make_float4(0.f, 0.f, 0.f, 0.f);

    for (int t = 0; t < T; t++) {
        As[kq + 0][lr] = aR.x; As[kq + 1][lr] = aR.y; As[kq + 2][lr] = aR.z; As[kq + 3][lr] = aR.w;
        Bs[kq + 0][lr] = bR.x; Bs[kq + 1][lr] = bR.y; Bs[kq + 2][lr] = bR.z; Bs[kq + 3][lr] = bR.w;
        __syncthreads();
        if (t + 1 < T) {
            aR = *(const float4*)(aptr + (t + 1) * 8);
            bR = bok ? *(const float4*)(bptr + (t + 1) * 8) : make_float4(0.f, 0.f, 0.f, 0.f);
        }
#pragma unroll
        for (int k = 0; k < 8; k++) {
            float4 a0 = *(const float4*)&As[k][ty * 4];
            float4 a1 = *(const float4*)&As[k][64 + ty * 4];
            ulonglong2 bp01 = *(const ulonglong2*)&Bs[k][tx * 4];
            ulonglong2 bp23 = *(const ulonglong2*)&Bs[k][64 + tx * 4];
            unsigned long long aa[8];
            aa[0] = splat2(a0.x); aa[1] = splat2(a0.y); aa[2] = splat2(a0.z); aa[3] = splat2(a0.w);
            aa[4] = splat2(a1.x); aa[5] = splat2(a1.y); aa[6] = splat2(a1.z); aa[7] = splat2(a1.w);
#pragma unroll
            for (int i = 0; i < 8; i++) {
                fma2(acc[i][0], aa[i], bp01.x);
                fma2(acc[i][1], aa[i], bp01.y);
                fma2(acc[i][2], aa[i], bp23.x);
                fma2(acc[i][3], aa[i], bp23.y);
            }
        }
        __syncthreads();
    }

#pragma unroll
    for (int i = 0; i < 8; i++) {
        int row = m0 + ((i < 4) ? (ty * 4 + i) : (64 + ty * 4 + (i - 4)));
#pragma unroll
        for (int jh = 0; jh < 2; jh++) {
            int col = n0 + (jh ? (64 + tx * 4) : (tx * 4));
            if (col < N) {
                float2 p0 = unpack2(acc[i][jh * 2 + 0]);
                float2 p1 = unpack2(acc[i][jh * 2 + 1]);
                float v0 = p0.x, v1 = p0.y, v2 = p1.x, v3 = p1.y;
                if (bias1) { v0 += bias1[col]; v1 += bias1[col + 1]; v2 += bias1[col + 2]; v3 += bias1[col + 3]; }
                if (bias2) { v0 += bias2[col]; v1 += bias2[col + 1]; v2 += bias2[col + 2]; v3 += bias2[col + 3]; }
                if (ACT == 1) { v0 = tanhf(v0); v1 = tanhf(v1); v2 = tanhf(v2); v3 = tanhf(v3); }
                float4 v; v.x = v0; v.y = v1; v.z = v2; v.w = v3;
                *(float4*)(&C[(long)row * N + col]) = v;
            }
        }
    }
}

// ---------------- one LSTM time step (R3 version) ----------------
#define HPAD 1028
#define STEP_SMEM ((32 * HPAD + 128 * 32) * 4)

__global__ void __launch_bounds__(256) lstm_step_kernel(
    const float* __restrict__ gin, const float* __restrict__ wht,
    const float* __restrict__ fp, const float* __restrict__ h0l,
    const float* __restrict__ c0l, float* __restrict__ x,
    float* __restrict__ cst, int s, int layer)
{
    extern __shared__ float sm[];
    float* hsm = sm;
    float* wsm = sm + 32 * HPAD;

    int tid = threadIdx.x;
    const float* hsrc = (s == 0) ? h0l : (x + (long)(s - 1) * Bb * Hh);

    for (int i = tid; i < (Bb * Hh) / 4; i += 256) {
        float4 v = *(const float4*)(hsrc + i * 4);
        int b = (i * 4) >> 10;
        int k = (i * 4) & 1023;
        *(float4*)(hsm + b * HPAD + k) = v;
    }

    int b = tid >> 3, jj = tid & 7;
    int j0 = blockIdx.x * 8;
    int j = j0 + jj;

    unsigned long long accA, accB;
    {
        long gbase = ((long)(s * Bb + b)) * 4096 + j;
        accA = pack2(gin[gbase],        gin[gbase + 1024]);
        accB = pack2(gin[gbase + 2048], gin[gbase + 3072]);
    }
    __syncthreads();

    for (int kc = 0; kc < 8; kc++) {
        for (int i = tid; i < 128 * 32; i += 256) {
            int kk = i >> 5;
            int r = i & 31;
            int gate = r >> 3;
            int jw = r & 7;
            wsm[kk * 32 + jw * 4 + gate] =
                wht[(long)(kc * 128 + kk) * 4096 + gate * 1024 + j0 + jw];
        }
        __syncthreads();
        const float* hrow = hsm + b * HPAD + kc * 128;
#pragma unroll 8
        for (int k4 = 0; k4 < 32; k4++) {
            float4 hv = *(const float4*)(hrow + k4 * 4);
            const unsigned long long* wb =
                (const unsigned long long*)(wsm + (k4 * 4) * 32 + jj * 4);
            unsigned long long ha;
            ha = splat2(hv.x);
            fma2(accA, ha, wb[0]);  fma2(accB, ha, wb[1]);
            ha = splat2(hv.y);
            fma2(accA, ha, wb[16]); fma2(accB, ha, wb[17]);
            ha = splat2(hv.z);
            fma2(accA, ha, wb[32]); fma2(accB, ha, wb[33]);
            ha = splat2(hv.w);
            fma2(accA, ha, wb[48]); fma2(accB, ha, wb[49]);
        }
        __syncthreads();
    }

    float2 pA = unpack2(accA);
    float2 pB = unpack2(accB);
    float i_ = sigmoidf_(pA.x);
    float f_ = sigmoidf_(pA.y);
    float g_ = tanhf(pB.x);
    float o_ = sigmoidf_(pB.y);
    float c_old = (s == 0) ? c0l[b * Hh + j] : cst[b * Hh + j];
    float h_old = hsm[b * HPAD + j];
    float cn = f_ * c_old + i_ * g_;
    float hn = o_ * tanhf(cn);
    float m = sigmoidf_((11.0f - fp[b * Ss + s]) * 0.25f - (float)layer);
    cn = cn * (1.0f - m) + c_old * m;
    hn = hn * (1.0f - m) + h_old * m;
    cst[b * Hh + j] = cn;
    x[((long)(s * Bb + b)) * Hh + j] = hn;
}

// ---------------- launch ----------------
extern "C" void kernel_launch(void* const* d_in, const int* in_sizes, int n_in,
                              void* d_out, int out_size) {
    (void)in_sizes; (void)n_in; (void)out_size;
    const int*   src   = (const int*)  d_in[0];
    const float* fixp  = (const float*)d_in[1];
    const float* emb   = (const float*)d_in[2];
    const float* W_lin = (const float*)d_in[3];
    const float* b_lin = (const float*)d_in[4];
    const float* W_ih  = (const float*)d_in[5];
    const float* W_hh  = (const float*)d_in[6];
    const float* b_ih  = (const float*)d_in[7];
    const float* b_hh  = (const float*)d_in[8];
    const float* fc_W1 = (const float*)d_in[9];
    const float* fc_b1 = (const float*)d_in[10];
    const float* fc_W2 = (const float*)d_in[11];
    const float* fc_b2 = (const float*)d_in[12];
    const float* h0    = (const float*)d_in[13];
    const float* c0    = (const float*)d_in[14];
    float* out = (float*)d_out;

    float *fp, *inputx, *inp, *x, *gin, *wht, *cst, *hid;
    __nv_bfloat16 *ahi, *alo, *bhi, *blo;
    cudaGetSymbolAddress((void**)&fp,     g_fp);
    cudaGetSymbolAddress((void**)&inputx, g_inputx);
    cudaGetSymbolAddress((void**)&inp,    g_inp);
    cudaGetSymbolAddress((void**)&x,      g_x);
    cudaGetSymbolAddress((void**)&gin,    g_gin);
    cudaGetSymbolAddress((void**)&wht,    g_wht);
    cudaGetSymbolAddress((void**)&cst,    g_c);
    cudaGetSymbolAddress((void**)&hid,    g_hid);
    cudaGetSymbolAddress((void**)&ahi,    g_ahi);
    cudaGetSymbolAddress((void**)&alo,    g_alo);
    cudaGetSymbolAddress((void**)&bhi,    g_bhi);
    cudaGetSymbolAddress((void**)&blo,    g_blo);

    cudaFuncSetAttribute(lstm_step_kernel,
                         cudaFuncAttributeMaxDynamicSharedMemorySize, STEP_SMEM);

    const int M = Ss * Bb;   // 8192

    // 1) layer norm of fix_pred
    ln_kernel<<<Bb, 256>>>(fixp, fp);

    // 2) input projection (SGEMM, small)
    sgemm_kernel<1, 0><<<dim3(Hh / 128, M / 128), 256>>>(
        emb, W_lin, inputx, b_lin, nullptr, M, Hh, Ee, src);

    // 3) three LSTM layers
    for (int l = 0; l < Ll; l++) {
        transpose_kernel<<<dim3(4 * Hh / 32, Hh / 32), dim3(32, 32)>>>(
            W_hh + (long)l * 4 * Hh * Hh, wht);
        ew_kernel<<<(M * Hh) / 256, 256>>>(x, inputx, fp, inp, l);
        // bf16 splits for tensor cores
        split_kernel<<<((long)M * Hh + 255) / 256, 256>>>(inp, ahi, alo, M, Hh, M);
        split_kernel<<<((long)4 * Hh * Hh + 255) / 256, 256>>>(
            W_ih + (long)l * 4 * Hh * Hh, bhi, blo, 4 * Hh, Hh, 4 * Hh);
        // gin = inp @ W_ih^T + b_ih + b_hh  (bf16x3 mma)
        tc_gemm_kernel<<<dim3(4 * Hh / 128, M / 128), 256>>>(
            ahi, alo, bhi, blo, gin,
            b_ih + (long)l * 4 * Hh, b_hh + (long)l * 4 * Hh, Hh, 4 * Hh);
        for (int s = 0; s < Ss; s++) {
            lstm_step_kernel<<<128, 256, STEP_SMEM>>>(
                gin, wht, fp, h0 + (long)l * Bb * Hh, c0 + (long)l * Bb * Hh,
                x, cst, s, l);
        }
    }

    // 4) fc1 with tanh (SGEMM, small; reorders [S,B,H] -> [B,S,E])
    sgemm_kernel<2, 1><<<dim3(Ee / 128, M / 128), 256>>>(
        x, fc_W1, hid, fc_b1, nullptr, M, Ee, Hh, nullptr);

    // 5) fc2 -> logits (bf16x3 mma, N padded 10000 -> 10112)
    split_kernel<<<((long)M * Ee + 255) / 256, 256>>>(hid, ahi, alo, M, Ee, M);
    split_kernel<<<((long)NPAD_FC2 * Ee + 255) / 256, 256>>>(
        fc_W2, bhi, blo, Vv, Ee, NPAD_FC2);
    tc_gemm_kernel<<<dim3(NPAD_FC2 / 128, M / 128), 256>>>(
        ahi, alo, bhi, blo, out, fc_b2, nullptr, Ee, Vv);
}

// round 8
// speedup vs baseline: 1.3595x; 1.0267x over previous
#include <cuda_runtime.h>
#include <cuda_fp16.h>
#include <math.h>
#include <stdint.h>

#define Bb 32
#define Ss 256
#define Vv 10000
#define Ee 512
#define Hh 1024
#define Ll 3

#define NPAD_FC2 10112   /* 79 * 128 */

// ---------------- scratch (static __device__ arrays; no allocation) ----------------
__device__ float g_fp[Bb * Ss];
__device__ float g_inputx[Ss * Bb * Hh];
__device__ float g_inp[Ss * Bb * Hh];
__device__ float g_x[Ss * Bb * Hh];
__device__ float g_gin[Ss * Bb * 4 * Hh];
__device__ float g_wht[Hh * 4 * Hh];
__device__ float g_c[Bb * Hh];
__device__ float g_hid[Bb * Ss * Ee];
// fp16 split scratch
__device__ __half g_ah[Ss * Bb * Hh];
__device__ __half g_al[Ss * Bb * Hh];
__device__ __half g_bw[NPAD_FC2 * Ee > 4 * Hh * Hh ? NPAD_FC2 * Ee : 4 * Hh * Hh];

__device__ __forceinline__ float sigmoidf_(float x) { return 1.0f / (1.0f + expf(-x)); }

// ---- packed f32x2 helpers ----
__device__ __forceinline__ unsigned long long splat2(float x) {
    unsigned long long r; asm("mov.b64 %0, {%1, %1};" : "=l"(r) : "f"(x)); return r;
}
__device__ __forceinline__ unsigned long long pack2(float x, float y) {
    unsigned long long r; asm("mov.b64 %0, {%1, %2};" : "=l"(r) : "f"(x), "f"(y)); return r;
}
__device__ __forceinline__ float2 unpack2(unsigned long long v) {
    float2 r; asm("mov.b64 {%0, %1}, %2;" : "=f"(r.x), "=f"(r.y) : "l"(v)); return r;
}
__device__ __forceinline__ void fma2(unsigned long long& d,
                                     unsigned long long a, unsigned long long b) {
    asm("fma.rn.f32x2 %0, %1, %2, %0;" : "+l"(d) : "l"(a), "l"(b));
}

__device__ __forceinline__ uint32_t smem_to_u32(const void* p) {
    uint32_t a;
    asm("{ .reg .u64 t; cvta.to.shared.u64 t, %1; cvt.u32.u64 %0, t; }" : "=r"(a) : "l"(p));
    return a;
}

// ---- warp-level tensor core + cp.async (baseline PTX, valid on target sm_103) ----
__device__ __forceinline__ void ldsm4(uint32_t& r0, uint32_t& r1, uint32_t& r2, uint32_t& r3,
                                      uint32_t addr) {
    asm volatile("ldmatrix.sync.aligned.m8n8.x4.shared.b16 {%0,%1,%2,%3}, [%4];"
                 : "=r"(r0), "=r"(r1), "=r"(r2), "=r"(r3) : "r"(addr));
}
__device__ __forceinline__ void mma16816h(float* d, const uint32_t* a, const uint32_t* b) {
    asm volatile(
        "mma.sync.aligned.m16n8k16.row.col.f32.f16.f16.f32 "
        "{%0,%1,%2,%3}, {%4,%5,%6,%7}, {%8,%9}, {%0,%1,%2,%3};"
        : "+f"(d[0]), "+f"(d[1]), "+f"(d[2]), "+f"(d[3])
        : "r"(a[0]), "r"(a[1]), "r"(a[2]), "r"(a[3]), "r"(b[0]), "r"(b[1]));
}
__device__ __forceinline__ void cpasync16(uint32_t s, const void* g) {
    asm volatile("cp.async.cg.shared.global [%0], [%1], 16;" :: "r"(s), "l"(g));
}
#define CP_COMMIT() asm volatile("cp.async.commit_group;" ::: "memory")
#define CP_WAIT1()  asm volatile("cp.async.wait_group 1;" ::: "memory")
#define CP_WAIT0()  asm volatile("cp.async.wait_group 0;" ::: "memory")

// ---------------- fp32 -> fp16 hi/lo split (A operand) ----------------
__global__ void splitA_f16(const float* __restrict__ in,
                           __half* __restrict__ hi, __half* __restrict__ lo, long n) {
    long idx = (long)blockIdx.x * 256 + threadIdx.x;
    if (idx >= n) return;
    float v = in[idx];
    __half h = __float2half_rn(v);
    hi[idx] = h;
    lo[idx] = __float2half_rn(v - __half2float(h));
}

// ---------------- fp32 -> fp16 single (B/weight operand, padded rows) ----------------
__global__ void cvtB_f16(const float* __restrict__ in, __half* __restrict__ out,
                         int rows, int cols, int rows_pad) {
    long idx = (long)blockIdx.x * 256 + threadIdx.x;
    long n = (long)rows_pad * cols;
    if (idx >= n) return;
    long row = idx / cols;
    out[idx] = __float2half_rn(row < rows ? in[idx] : 0.0f);
}

// ---------------- tensor-core GEMM: C[M,Nout] = A[M,K]*B[Npad,K]^T (+biases) -------
// fp16 asymmetric split: C ~= Ahi*B + Alo*B, fp32 accumulate via mma.m16n8k16.
// CTA 128x128, 8 warps (warp tile 32x64), K chunk 32, cp.async double buffering.
#define TCRS   80                  /* smem row stride bytes (64B data + 16B pad) */
#define TCTILE (128 * TCRS)        /* 10240 B per tile */
#define TC_SMEM (2 * 3 * TCTILE)   /* 2 stages x (AH | AL | B) = 61440 B */

__global__ void __launch_bounds__(256) tc_gemm_kernel(
    const __half* __restrict__ ah, const __half* __restrict__ al,
    const __half* __restrict__ bw,
    float* __restrict__ C,
    const float* __restrict__ bias1, const float* __restrict__ bias2,
    int K, int Nout)
{
    extern __shared__ char smem[];
    uint32_t sbase = smem_to_u32(smem);

    int tid = threadIdx.x, lane = tid & 31, w = tid >> 5;
    int wm = w & 3, wn = w >> 2;
    int m0 = blockIdx.y * 128, n0 = blockIdx.x * 128;

    // staging: each thread covers 32B (two 16B segs) of one row per tile
    int srow = tid >> 1;               // 0..127
    int sun  = (tid & 1) * 2;          // 16B-unit 0 or 2
    const __half* gAh = ah + (long)(m0 + srow) * K + sun * 8;
    const __half* gAl = al + (long)(m0 + srow) * K + sun * 8;
    const __half* gB  = bw + (long)(n0 + srow) * K + sun * 8;
    int sofs = srow * TCRS + sun * 16;

    // ldmatrix lane addressing (row-pad 80B -> conflict-free phases)
    int lrow = lane & 15;
    int lcol = (lane >> 4) * 16;
    uint32_t aoff = (uint32_t)((wm * 32 + lrow) * TCRS + lcol);
    uint32_t boff = (uint32_t)(2 * TCTILE + (wn * 64 + lrow) * TCRS + lcol);

    float acc[2][8][4];
#pragma unroll
    for (int mt = 0; mt < 2; mt++)
#pragma unroll
        for (int nt = 0; nt < 8; nt++)
#pragma unroll
            for (int q = 0; q < 4; q++) acc[mt][nt][q] = 0.0f;

    int NC = K / 32;

    // prologue: issue chunk 0 into stage 0
    {
        uint32_t base = sbase;
        cpasync16(base + sofs,                  gAh);
        cpasync16(base + sofs + 16,             gAh + 8);
        cpasync16(base + TCTILE + sofs,         gAl);
        cpasync16(base + TCTILE + sofs + 16,    gAl + 8);
        cpasync16(base + 2*TCTILE + sofs,       gB);
        cpasync16(base + 2*TCTILE + sofs + 16,  gB + 8);
        CP_COMMIT();
    }

    for (int kc = 0; kc < NC; kc++) {
        int st = kc & 1;
        if (kc + 1 < NC) {
            uint32_t base = sbase + ((kc + 1) & 1) * (3 * TCTILE);
            long o = (long)(kc + 1) * 32;
            cpasync16(base + sofs,                  gAh + o);
            cpasync16(base + sofs + 16,             gAh + o + 8);
            cpasync16(base + TCTILE + sofs,         gAl + o);
            cpasync16(base + TCTILE + sofs + 16,    gAl + o + 8);
            cpasync16(base + 2*TCTILE + sofs,       gB + o);
            cpasync16(base + 2*TCTILE + sofs + 16,  gB + o + 8);
            CP_COMMIT();
            CP_WAIT1();
        } else {
            CP_WAIT0();
        }
        __syncthreads();

        uint32_t stb = sbase + st * (3 * TCTILE);
#pragma unroll
        for (int k16 = 0; k16 < 2; k16++) {
            uint32_t AH[2][4], AL[2][4];
#pragma unroll
            for (int mt = 0; mt < 2; mt++) {
                uint32_t a0 = stb + aoff + mt * (16 * TCRS) + k16 * 32;
                ldsm4(AH[mt][0], AH[mt][1], AH[mt][2], AH[mt][3], a0);
                ldsm4(AL[mt][0], AL[mt][1], AL[mt][2], AL[mt][3], a0 + TCTILE);
            }
            uint32_t Bf[8][2];
#pragma unroll
            for (int np = 0; np < 4; np++) {
                uint32_t t0, t1, t2, t3;
                uint32_t b0 = stb + boff + np * (16 * TCRS) + k16 * 32;
                ldsm4(t0, t1, t2, t3, b0);
                Bf[np*2][0] = t0; Bf[np*2][1] = t2;
                Bf[np*2+1][0] = t1; Bf[np*2+1][1] = t3;
            }
            // pass 1: Ahi * B
#pragma unroll
            for (int mt = 0; mt < 2; mt++)
#pragma unroll
                for (int nt = 0; nt < 8; nt++)
                    mma16816h(acc[mt][nt], AH[mt], Bf[nt]);
            // pass 2: Alo * B
#pragma unroll
            for (int mt = 0; mt < 2; mt++)
#pragma unroll
                for (int nt = 0; nt < 8; nt++)
                    mma16816h(acc[mt][nt], AL[mt], Bf[nt]);
        }
        __syncthreads();
    }

    // epilogue: d0/d1 -> (row g, col c..c+1), d2/d3 -> (row g+8)
    int g = lane >> 2, tq = lane & 3;
#pragma unroll
    for (int mt = 0; mt < 2; mt++) {
        int row0 = m0 + wm * 32 + mt * 16 + g;
#pragma unroll
        for (int nt = 0; nt < 8; nt++) {
            int col = n0 + wn * 64 + nt * 8 + tq * 2;
            if (col < Nout) {
                float b1v0 = bias1 ? bias1[col]     : 0.0f;
                float b1v1 = bias1 ? bias1[col + 1] : 0.0f;
                if (bias2) { b1v0 += bias2[col]; b1v1 += bias2[col + 1]; }
                float2 v01; v01.x = acc[mt][nt][0] + b1v0; v01.y = acc[mt][nt][1] + b1v1;
                float2 v23; v23.x = acc[mt][nt][2] + b1v0; v23.y = acc[mt][nt][3] + b1v1;
                *(float2*)(&C[(long)row0 * Nout + col]) = v01;
                *(float2*)(&C[(long)(row0 + 8) * Nout + col]) = v23;
            }
        }
    }
}

// ---------------- layer norm over seq dim ----------------
__global__ void ln_kernel(const float* __restrict__ fixp, float* __restrict__ fp) {
    __shared__ float red[256];
    int b = blockIdx.x, s = threadIdx.x;
    float v = fixp[b * Ss + s];
    red[s] = v;
    __syncthreads();
    for (int o = 128; o > 0; o >>= 1) { if (s < o) red[s] += red[s + o]; __syncthreads(); }
    float mu = red[0] * (1.0f / Ss);
    __syncthreads();
    float d = v - mu;
    red[s] = d * d;
    __syncthreads();
    for (int o = 128; o > 0; o >>= 1) { if (s < o) red[s] += red[s + o]; __syncthreads(); }
    float var = red[0] * (1.0f / Ss);
    float y = d * rsqrtf(var + 1e-5f);
    fp[b * Ss + s] = (y + 1.96f) / 3.92f * 12.0f;
}

// ---------------- W_hh transpose: [4H,H] -> [H,4H] ----------------
__global__ void transpose_kernel(const float* __restrict__ in, float* __restrict__ out) {
    __shared__ float t[32][33];
    int n0 = blockIdx.x * 32, k0 = blockIdx.y * 32;
    int tx = threadIdx.x, ty = threadIdx.y;
    t[ty][tx] = in[(n0 + ty) * Hh + (k0 + tx)];
    __syncthreads();
    out[(size_t)(k0 + ty) * (4 * Hh) + (n0 + tx)] = t[tx][ty];
}

// ---------------- gated input blend ----------------
__global__ void ew_kernel(const float* __restrict__ x, const float* __restrict__ ix,
                          const float* __restrict__ fp, float* __restrict__ inp, int layer) {
    int idx = blockIdx.x * 256 + threadIdx.x;
    int sb = idx >> 10;
    int b = sb & 31;
    int s = sb >> 5;
    float alpha = (11.0f - fp[b * Ss + s]) * 0.25f - (float)layer;
    float mask = sigmoidf_(alpha);
    float gate = sigmoidf_(alpha + 1.0f) - mask;
    float xv = (layer == 0) ? 0.0f : x[idx];
    inp[idx] = xv * (1.0f - gate) + ix[idx] * gate;
}

// ---------------- SGEMM (R3 version) for small GEMMs ----------------
template <int MODE, int ACT>
__global__ void __launch_bounds__(256) sgemm_kernel(
    const float* __restrict__ A, const float* __restrict__ Bm, float* __restrict__ C,
    const float* __restrict__ bias1, const float* __restrict__ bias2,
    int M, int N, int K, const int* __restrict__ src)
{
    __shared__ float As[8][128];
    __shared__ float Bs[8][128];
    int tid = threadIdx.x;
    int m0 = blockIdx.y * 128, n0 = blockIdx.x * 128;

    int lr = tid >> 1;
    int kq = (tid & 1) * 4;

    int am = m0 + lr;
    long arow;
    if (MODE == 1)      { int b = am & 31;  int s = am >> 5; arow = src[b * Ss + s]; }
    else if (MODE == 2) { int s = am & 255; int b = am >> 8; arow = (long)s * Bb + b; }
    else                { arow = am; }
    const float* aptr = A + arow * (long)K + kq;

    int bn = n0 + lr;
    bool bok = (bn < N);
    const float* bptr = Bm + (long)bn * K + kq;

    int tx = tid & 15, ty = tid >> 4;

    unsigned long long acc[8][4];
#pragma unroll
    for (int i = 0; i < 8; i++)
#pragma unroll
        for (int j = 0; j < 4; j++) acc[i][j] = 0ULL;

    int T = K / 8;
    float4 aR = *(const float4*)(aptr);
    float4 bR = bok ? *(const float4*)(bptr) : make_float4(0.f, 0.f, 0.f, 0.f);

    for (int t = 0; t < T; t++) {
        As[kq + 0][lr] = aR.x; As[kq + 1][lr] = aR.y; As[kq + 2][lr] = aR.z; As[kq + 3][lr] = aR.w;
        Bs[kq + 0][lr] = bR.x; Bs[kq + 1][lr] = bR.y; Bs[kq + 2][lr] = bR.z; Bs[kq + 3][lr] = bR.w;
        __syncthreads();
        if (t + 1 < T) {
            aR = *(const float4*)(aptr + (t + 1) * 8);
            bR = bok ? *(const float4*)(bptr + (t + 1) * 8) : make_float4(0.f, 0.f, 0.f, 0.f);
        }
#pragma unroll
        for (int k = 0; k < 8; k++) {
            float4 a0 = *(const float4*)&As[k][ty * 4];
            float4 a1 = *(const float4*)&As[k][64 + ty * 4];
            ulonglong2 bp01 = *(const ulonglong2*)&Bs[k][tx * 4];
            ulonglong2 bp23 = *(const ulonglong2*)&Bs[k][64 + tx * 4];
            unsigned long long aa[8];
            aa[0] = splat2(a0.x); aa[1] = splat2(a0.y); aa[2] = splat2(a0.z); aa[3] = splat2(a0.w);
            aa[4] = splat2(a1.x); aa[5] = splat2(a1.y); aa[6] = splat2(a1.z); aa[7] = splat2(a1.w);
#pragma unroll
            for (int i = 0; i < 8; i++) {
                fma2(acc[i][0], aa[i], bp01.x);
                fma2(acc[i][1], aa[i], bp01.y);
                fma2(acc[i][2], aa[i], bp23.x);
                fma2(acc[i][3], aa[i], bp23.y);
            }
        }
        __syncthreads();
    }

#pragma unroll
    for (int i = 0; i < 8; i++) {
        int row = m0 + ((i < 4) ? (ty * 4 + i) : (64 + ty * 4 + (i - 4)));
#pragma unroll
        for (int jh = 0; jh < 2; jh++) {
            int col = n0 + (jh ? (64 + tx * 4) : (tx * 4));
            if (col < N) {
                float2 p0 = unpack2(acc[i][jh * 2 + 0]);
                float2 p1 = unpack2(acc[i][jh * 2 + 1]);
                float v0 = p0.x, v1 = p0.y, v2 = p1.x, v3 = p1.y;
                if (bias1) { v0 += bias1[col]; v1 += bias1[col + 1]; v2 += bias1[col + 2]; v3 += bias1[col + 3]; }
                if (bias2) { v0 += bias2[col]; v1 += bias2[col + 1]; v2 += bias2[col + 2]; v3 += bias2[col + 3]; }
                if (ACT == 1) { v0 = tanhf(v0); v1 = tanhf(v1); v2 = tanhf(v2); v3 = tanhf(v3); }
                float4 v; v.x = v0; v.y = v1; v.z = v2; v.w = v3;
                *(float4*)(&C[(long)row * N + col]) = v;
            }
        }
    }
}

// ---------------- one LSTM time step (R3 version) ----------------
#define HPAD 1028
#define STEP_SMEM ((32 * HPAD + 128 * 32) * 4)

__global__ void __launch_bounds__(256) lstm_step_kernel(
    const float* __restrict__ gin, const float* __restrict__ wht,
    const float* __restrict__ fp, const float* __restrict__ h0l,
    const float* __restrict__ c0l, float* __restrict__ x,
    float* __restrict__ cst, int s, int layer)
{
    extern __shared__ float sm[];
    float* hsm = sm;
    float* wsm = sm + 32 * HPAD;

    int tid = threadIdx.x;
    const float* hsrc = (s == 0) ? h0l : (x + (long)(s - 1) * Bb * Hh);

    for (int i = tid; i < (Bb * Hh) / 4; i += 256) {
        float4 v = *(const float4*)(hsrc + i * 4);
        int b = (i * 4) >> 10;
        int k = (i * 4) & 1023;
        *(float4*)(hsm + b * HPAD + k) = v;
    }

    int b = tid >> 3, jj = tid & 7;
    int j0 = blockIdx.x * 8;
    int j = j0 + jj;

    unsigned long long accA, accB;
    {
        long gbase = ((long)(s * Bb + b)) * 4096 + j;
        accA = pack2(gin[gbase],        gin[gbase + 1024]);
        accB = pack2(gin[gbase + 2048], gin[gbase + 3072]);
    }
    __syncthreads();

    for (int kc = 0; kc < 8; kc++) {
        for (int i = tid; i < 128 * 32; i += 256) {
            int kk = i >> 5;
            int r = i & 31;
            int gate = r >> 3;
            int jw = r & 7;
            wsm[kk * 32 + jw * 4 + gate] =
                wht[(long)(kc * 128 + kk) * 4096 + gate * 1024 + j0 + jw];
        }
        __syncthreads();
        const float* hrow = hsm + b * HPAD + kc * 128;
#pragma unroll 8
        for (int k4 = 0; k4 < 32; k4++) {
            float4 hv = *(const float4*)(hrow + k4 * 4);
            const unsigned long long* wb =
                (const unsigned long long*)(wsm + (k4 * 4) * 32 + jj * 4);
            unsigned long long ha;
            ha = splat2(hv.x);
            fma2(accA, ha, wb[0]);  fma2(accB, ha, wb[1]);
            ha = splat2(hv.y);
            fma2(accA, ha, wb[16]); fma2(accB, ha, wb[17]);
            ha = splat2(hv.z);
            fma2(accA, ha, wb[32]); fma2(accB, ha, wb[33]);
            ha = splat2(hv.w);
            fma2(accA, ha, wb[48]); fma2(accB, ha, wb[49]);
        }
        __syncthreads();
    }

    float2 pA = unpack2(accA);
    float2 pB = unpack2(accB);
    float i_ = sigmoidf_(pA.x);
    float f_ = sigmoidf_(pA.y);
    float g_ = tanhf(pB.x);
    float o_ = sigmoidf_(pB.y);
    float c_old = (s == 0) ? c0l[b * Hh + j] : cst[b * Hh + j];
    float h_old = hsm[b * HPAD + j];
    float cn = f_ * c_old + i_ * g_;
    float hn = o_ * tanhf(cn);
    float m = sigmoidf_((11.0f - fp[b * Ss + s]) * 0.25f - (float)layer);
    cn = cn * (1.0f - m) + c_old * m;
    hn = hn * (1.0f - m) + h_old * m;
    cst[b * Hh + j] = cn;
    x[((long)(s * Bb + b)) * Hh + j] = hn;
}

// ---------------- launch ----------------
extern "C" void kernel_launch(void* const* d_in, const int* in_sizes, int n_in,
                              void* d_out, int out_size) {
    (void)in_sizes; (void)n_in; (void)out_size;
    const int*   src   = (const int*)  d_in[0];
    const float* fixp  = (const float*)d_in[1];
    const float* emb   = (const float*)d_in[2];
    const float* W_lin = (const float*)d_in[3];
    const float* b_lin = (const float*)d_in[4];
    const float* W_ih  = (const float*)d_in[5];
    const float* W_hh  = (const float*)d_in[6];
    const float* b_ih  = (const float*)d_in[7];
    const float* b_hh  = (const float*)d_in[8];
    const float* fc_W1 = (const float*)d_in[9];
    const float* fc_b1 = (const float*)d_in[10];
    const float* fc_W2 = (const float*)d_in[11];
    const float* fc_b2 = (const float*)d_in[12];
    const float* h0    = (const float*)d_in[13];
    const float* c0    = (const float*)d_in[14];
    float* out = (float*)d_out;

    float *fp, *inputx, *inp, *x, *gin, *wht, *cst, *hid;
    __half *ah, *al, *bw;
    cudaGetSymbolAddress((void**)&fp,     g_fp);
    cudaGetSymbolAddress((void**)&inputx, g_inputx);
    cudaGetSymbolAddress((void**)&inp,    g_inp);
    cudaGetSymbolAddress((void**)&x,      g_x);
    cudaGetSymbolAddress((void**)&gin,    g_gin);
    cudaGetSymbolAddress((void**)&wht,    g_wht);
    cudaGetSymbolAddress((void**)&cst,    g_c);
    cudaGetSymbolAddress((void**)&hid,    g_hid);
    cudaGetSymbolAddress((void**)&ah,     g_ah);
    cudaGetSymbolAddress((void**)&al,     g_al);
    cudaGetSymbolAddress((void**)&bw,     g_bw);

    cudaFuncSetAttribute(lstm_step_kernel,
                         cudaFuncAttributeMaxDynamicSharedMemorySize, STEP_SMEM);
    cudaFuncSetAttribute(tc_gemm_kernel,
                         cudaFuncAttributeMaxDynamicSharedMemorySize, TC_SMEM);

    const int M = Ss * Bb;   // 8192

    // 1) layer norm of fix_pred
    ln_kernel<<<Bb, 256>>>(fixp, fp);

    // 2) input projection (SGEMM, small)
    sgemm_kernel<1, 0><<<dim3(Hh / 128, M / 128), 256>>>(
        emb, W_lin, inputx, b_lin, nullptr, M, Hh, Ee, src);

    // 3) three LSTM layers
    for (int l = 0; l < Ll; l++) {
        transpose_kernel<<<dim3(4 * Hh / 32, Hh / 32), dim3(32, 32)>>>(
            W_hh + (long)l * 4 * Hh * Hh, wht);
        ew_kernel<<<(M * Hh) / 256, 256>>>(x, inputx, fp, inp, l);
        // fp16 splits for tensor cores
        splitA_f16<<<((long)M * Hh + 255) / 256, 256>>>(inp, ah, al, (long)M * Hh);
        cvtB_f16<<<((long)4 * Hh * Hh + 255) / 256, 256>>>(
            W_ih + (long)l * 4 * Hh * Hh, bw, 4 * Hh, Hh, 4 * Hh);
        // gin = inp @ W_ih^T + b_ih + b_hh  (fp16 2-pass mma)
        tc_gemm_kernel<<<dim3(4 * Hh / 128, M / 128), 256, TC_SMEM>>>(
            ah, al, bw, gin,
            b_ih + (long)l * 4 * Hh, b_hh + (long)l * 4 * Hh, Hh, 4 * Hh);
        for (int s = 0; s < Ss; s++) {
            lstm_step_kernel<<<128, 256, STEP_SMEM>>>(
                gin, wht, fp, h0 + (long)l * Bb * Hh, c0 + (long)l * Bb * Hh,
                x, cst, s, l);
        }
    }

    // 4) fc1 with tanh (SGEMM, small; reorders [S,B,H] -> [B,S,E])
    sgemm_kernel<2, 1><<<dim3(Ee / 128, M / 128), 256>>>(
        x, fc_W1, hid, fc_b1, nullptr, M, Ee, Hh, nullptr);

    // 5) fc2 -> logits (fp16 2-pass mma, N padded 10000 -> 10112)
    splitA_f16<<<((long)M * Ee + 255) / 256, 256>>>(hid, ah, al, (long)M * Ee);
    cvtB_f16<<<((long)NPAD_FC2 * Ee + 255) / 256, 256>>>(
        fc_W2, bw, Vv, Ee, NPAD_FC2);
    tc_gemm_kernel<<<dim3(NPAD_FC2 / 128, M / 128), 256, TC_SMEM>>>(
        ah, al, bw, out, fc_b2, nullptr, Ee, Vv);
}

// round 13
// speedup vs baseline: 1.8894x; 1.3897x over previous
#include <cuda_runtime.h>
#include <cuda_fp16.h>
#include <cooperative_groups.h>
#include <math.h>
#include <stdint.h>

namespace cg = cooperative_groups;

#define Bb 32
#define Ss 256
#define Vv 10000
#define Ee 512
#define Hh 1024
#define Ll 3

#define NPAD_FC2 10112   /* 79 * 128 */

// ---------------- scratch (static __device__ arrays; no allocation) ----------------
__device__ float g_fp[Bb * Ss];
__device__ float g_inputx[Ss * Bb * Hh];
__device__ float g_x[Ss * Bb * Hh];
__device__ float g_gin[Ss * Bb * 4 * Hh];
__device__ float g_hid[Bb * Ss * Ee];
// fp16 split scratch
__device__ __half g_ah[Ss * Bb * Hh];
__device__ __half g_al[Ss * Bb * Hh];
__device__ __half g_bw[NPAD_FC2 * Ee > 4 * Hh * Hh ? NPAD_FC2 * Ee : 4 * Hh * Hh];

__device__ __forceinline__ float sigmoidf_(float x) { return 1.0f / (1.0f + expf(-x)); }

// ---- packed f32x2 helpers ----
__device__ __forceinline__ unsigned long long splat2(float x) {
    unsigned long long r; asm("mov.b64 %0, {%1, %1};" : "=l"(r) : "f"(x)); return r;
}
__device__ __forceinline__ unsigned long long pack2(float x, float y) {
    unsigned long long r; asm("mov.b64 %0, {%1, %2};" : "=l"(r) : "f"(x), "f"(y)); return r;
}
__device__ __forceinline__ float2 unpack2(unsigned long long v) {
    float2 r; asm("mov.b64 {%0, %1}, %2;" : "=f"(r.x), "=f"(r.y) : "l"(v)); return r;
}
__device__ __forceinline__ void fma2(unsigned long long& d,
                                     unsigned long long a, unsigned long long b) {
    asm("fma.rn.f32x2 %0, %1, %2, %0;" : "+l"(d) : "l"(a), "l"(b));
}

__device__ __forceinline__ uint32_t smem_to_u32(const void* p) {
    uint32_t a;
    asm("{ .reg .u64 t; cvta.to.shared.u64 t, %1; cvt.u32.u64 %0, t; }" : "=r"(a) : "l"(p));
    return a;
}

// ---- L2-coherent loads (bypass L1) for cross-CTA-written data ----
__device__ __forceinline__ float4 ldcg4(const float* p) {
    float4 v;
    asm volatile("ld.global.cg.v4.f32 {%0,%1,%2,%3}, [%4];"
                 : "=f"(v.x), "=f"(v.y), "=f"(v.z), "=f"(v.w) : "l"(p));
    return v;
}
__device__ __forceinline__ float ldcg1(const float* p) {
    float v;
    asm volatile("ld.global.cg.f32 %0, [%1];" : "=f"(v) : "l"(p));
    return v;
}

// ---- warp-level tensor core + cp.async (baseline PTX, valid on target sm_103) ----
__device__ __forceinline__ void ldsm4(uint32_t& r0, uint32_t& r1, uint32_t& r2, uint32_t& r3,
                                      uint32_t addr) {
    asm volatile("ldmatrix.sync.aligned.m8n8.x4.shared.b16 {%0,%1,%2,%3}, [%4];"
                 : "=r"(r0), "=r"(r1), "=r"(r2), "=r"(r3) : "r"(addr));
}
__device__ __forceinline__ void mma16816h(float* d, const uint32_t* a, const uint32_t* b) {
    asm volatile(
        "mma.sync.aligned.m16n8k16.row.col.f32.f16.f16.f32 "
        "{%0,%1,%2,%3}, {%4,%5,%6,%7}, {%8,%9}, {%0,%1,%2,%3};"
        : "+f"(d[0]), "+f"(d[1]), "+f"(d[2]), "+f"(d[3])
        : "r"(a[0]), "r"(a[1]), "r"(a[2]), "r"(a[3]), "r"(b[0]), "r"(b[1]));
}
__device__ __forceinline__ void cpasync16(uint32_t s, const void* g) {
    asm volatile("cp.async.cg.shared.global [%0], [%1], 16;" :: "r"(s), "l"(g));
}
#define CP_COMMIT() asm volatile("cp.async.commit_group;" ::: "memory")
#define CP_WAIT1()  asm volatile("cp.async.wait_group 1;" ::: "memory")
#define CP_WAIT0()  asm volatile("cp.async.wait_group 0;" ::: "memory")

// ---------------- fused gated blend + fp16 hi/lo split ----------------
__global__ void ew_split(const float* __restrict__ x, const float* __restrict__ ix,
                         const float* __restrict__ fp,
                         __half* __restrict__ hi, __half* __restrict__ lo, int layer) {
    long idx = (long)blockIdx.x * 256 + threadIdx.x;
    int sb = (int)(idx >> 10);
    int b = sb & 31, s = sb >> 5;
    float alpha = (11.0f - fp[b * Ss + s]) * 0.25f - (float)layer;
    float mask = sigmoidf_(alpha);
    float gate = sigmoidf_(alpha + 1.0f) - mask;
    float xv = (layer == 0) ? 0.0f : x[idx];
    float v = xv * (1.0f - gate) + ix[idx] * gate;
    __half h = __float2half_rn(v);
    hi[idx] = h;
    lo[idx] = __float2half_rn(v - __half2float(h));
}

// ---------------- fp32 -> fp16 hi/lo split (A operand) ----------------
__global__ void splitA_f16(const float* __restrict__ in,
                           __half* __restrict__ hi, __half* __restrict__ lo, long n) {
    long idx = (long)blockIdx.x * 256 + threadIdx.x;
    if (idx >= n) return;
    float v = in[idx];
    __half h = __float2half_rn(v);
    hi[idx] = h;
    lo[idx] = __float2half_rn(v - __half2float(h));
}

// ---------------- fp32 -> fp16 single (B/weight operand, padded rows) ----------------
__global__ void cvtB_f16(const float* __restrict__ in, __half* __restrict__ out,
                         int rows, int cols, int rows_pad) {
    long idx = (long)blockIdx.x * 256 + threadIdx.x;
    long n = (long)rows_pad * cols;
    if (idx >= n) return;
    long row = idx / cols;
    out[idx] = __float2half_rn(row < rows ? in[idx] : 0.0f);
}

// ---------------- tensor-core GEMM (R8, unchanged) ----------------
#define TCRS   80
#define TCTILE (128 * TCRS)
#define TC_SMEM (2 * 3 * TCTILE)

__global__ void __launch_bounds__(256) tc_gemm_kernel(
    const __half* __restrict__ ah, const __half* __restrict__ al,
    const __half* __restrict__ bw,
    float* __restrict__ C,
    const float* __restrict__ bias1, const float* __restrict__ bias2,
    int K, int Nout)
{
    extern __shared__ char smem[];
    uint32_t sbase = smem_to_u32(smem);

    int tid = threadIdx.x, lane = tid & 31, w = tid >> 5;
    int wm = w & 3, wn = w >> 2;
    int m0 = blockIdx.y * 128, n0 = blockIdx.x * 128;

    int srow = tid >> 1;
    int sun  = (tid & 1) * 2;
    const __half* gAh = ah + (long)(m0 + srow) * K + sun * 8;
    const __half* gAl = al + (long)(m0 + srow) * K + sun * 8;
    const __half* gB  = bw + (long)(n0 + srow) * K + sun * 8;
    int sofs = srow * TCRS + sun * 16;

    int lrow = lane & 15;
    int lcol = (lane >> 4) * 16;
    uint32_t aoff = (uint32_t)((wm * 32 + lrow) * TCRS + lcol);
    uint32_t boff = (uint32_t)(2 * TCTILE + (wn * 64 + lrow) * TCRS + lcol);

    float acc[2][8][4];
#pragma unroll
    for (int mt = 0; mt < 2; mt++)
#pragma unroll
        for (int nt = 0; nt < 8; nt++)
#pragma unroll
            for (int q = 0; q < 4; q++) acc[mt][nt][q] = 0.0f;

    int NC = K / 32;

    {
        uint32_t base = sbase;
        cpasync16(base + sofs,                  gAh);
        cpasync16(base + sofs + 16,             gAh + 8);
        cpasync16(base + TCTILE + sofs,         gAl);
        cpasync16(base + TCTILE + sofs + 16,    gAl + 8);
        cpasync16(base + 2*TCTILE + sofs,       gB);
        cpasync16(base + 2*TCTILE + sofs + 16,  gB + 8);
        CP_COMMIT();
    }

    for (int kc = 0; kc < NC; kc++) {
        int st = kc & 1;
        if (kc + 1 < NC) {
            uint32_t base = sbase + ((kc + 1) & 1) * (3 * TCTILE);
            long o = (long)(kc + 1) * 32;
            cpasync16(base + sofs,                  gAh + o);
            cpasync16(base + sofs + 16,             gAh + o + 8);
            cpasync16(base + TCTILE + sofs,         gAl + o);
            cpasync16(base + TCTILE + sofs + 16,    gAl + o + 8);
            cpasync16(base + 2*TCTILE + sofs,       gB + o);
            cpasync16(base + 2*TCTILE + sofs + 16,  gB + o + 8);
            CP_COMMIT();
            CP_WAIT1();
        } else {
            CP_WAIT0();
        }
        __syncthreads();

        uint32_t stb = sbase + st * (3 * TCTILE);
#pragma unroll
        for (int k16 = 0; k16 < 2; k16++) {
            uint32_t AH[2][4], AL[2][4];
#pragma unroll
            for (int mt = 0; mt < 2; mt++) {
                uint32_t a0 = stb + aoff + mt * (16 * TCRS) + k16 * 32;
                ldsm4(AH[mt][0], AH[mt][1], AH[mt][2], AH[mt][3], a0);
                ldsm4(AL[mt][0], AL[mt][1], AL[mt][2], AL[mt][3], a0 + TCTILE);
            }
            uint32_t Bf[8][2];
#pragma unroll
            for (int np = 0; np < 4; np++) {
                uint32_t t0, t1, t2, t3;
                uint32_t b0 = stb + boff + np * (16 * TCRS) + k16 * 32;
                ldsm4(t0, t1, t2, t3, b0);
                Bf[np*2][0] = t0; Bf[np*2][1] = t2;
                Bf[np*2+1][0] = t1; Bf[np*2+1][1] = t3;
            }
#pragma unroll
            for (int mt = 0; mt < 2; mt++)
#pragma unroll
                for (int nt = 0; nt < 8; nt++)
                    mma16816h(acc[mt][nt], AH[mt], Bf[nt]);
#pragma unroll
            for (int mt = 0; mt < 2; mt++)
#pragma unroll
                for (int nt = 0; nt < 8; nt++)
                    mma16816h(acc[mt][nt], AL[mt], Bf[nt]);
        }
        __syncthreads();
    }

    int g = lane >> 2, tq = lane & 3;
#pragma unroll
    for (int mt = 0; mt < 2; mt++) {
        int row0 = m0 + wm * 32 + mt * 16 + g;
#pragma unroll
        for (int nt = 0; nt < 8; nt++) {
            int col = n0 + wn * 64 + nt * 8 + tq * 2;
            if (col < Nout) {
                float b1v0 = bias1 ? bias1[col]     : 0.0f;
                float b1v1 = bias1 ? bias1[col + 1] : 0.0f;
                if (bias2) { b1v0 += bias2[col]; b1v1 += bias2[col + 1]; }
                float2 v01; v01.x = acc[mt][nt][0] + b1v0; v01.y = acc[mt][nt][1] + b1v1;
                float2 v23; v23.x = acc[mt][nt][2] + b1v0; v23.y = acc[mt][nt][3] + b1v1;
                *(float2*)(&C[(long)row0 * Nout + col]) = v01;
                *(float2*)(&C[(long)(row0 + 8) * Nout + col]) = v23;
            }
        }
    }
}

// ---------------- layer norm over seq dim ----------------
__global__ void ln_kernel(const float* __restrict__ fixp, float* __restrict__ fp) {
    __shared__ float red[256];
    int b = blockIdx.x, s = threadIdx.x;
    float v = fixp[b * Ss + s];
    red[s] = v;
    __syncthreads();
    for (int o = 128; o > 0; o >>= 1) { if (s < o) red[s] += red[s + o]; __syncthreads(); }
    float mu = red[0] * (1.0f / Ss);
    __syncthreads();
    float d = v - mu;
    red[s] = d * d;
    __syncthreads();
    for (int o = 128; o > 0; o >>= 1) { if (s < o) red[s] += red[s + o]; __syncthreads(); }
    float var = red[0] * (1.0f / Ss);
    float y = d * rsqrtf(var + 1e-5f);
    fp[b * Ss + s] = (y + 1.96f) / 3.92f * 12.0f;
}

// ---------------- SGEMM (R3 version) for small GEMMs ----------------
template <int MODE, int ACT>
__global__ void __launch_bounds__(256) sgemm_kernel(
    const float* __restrict__ A, const float* __restrict__ Bm, float* __restrict__ C,
    const float* __restrict__ bias1, const float* __restrict__ bias2,
    int M, int N, int K, const int* __restrict__ src)
{
    __shared__ float As[8][128];
    __shared__ float Bs[8][128];
    int tid = threadIdx.x;
    int m0 = blockIdx.y * 128, n0 = blockIdx.x * 128;

    int lr = tid >> 1;
    int kq = (tid & 1) * 4;

    int am = m0 + lr;
    long arow;
    if (MODE == 1)      { int b = am & 31;  int s = am >> 5; arow = src[b * Ss + s]; }
    else if (MODE == 2) { int s = am & 255; int b = am >> 8; arow = (long)s * Bb + b; }
    else                { arow = am; }
    const float* aptr = A + arow * (long)K + kq;

    int bn = n0 + lr;
    bool bok = (bn < N);
    const float* bptr = Bm + (long)bn * K + kq;

    int tx = tid & 15, ty = tid >> 4;

    unsigned long long acc[8][4];
#pragma unroll
    for (int i = 0; i < 8; i++)
#pragma unroll
        for (int j = 0; j < 4; j++) acc[i][j] = 0ULL;

    int T = K / 8;
    float4 aR = *(const float4*)(aptr);
    float4 bR = bok ? *(const float4*)(bptr) : make_float4(0.f, 0.f, 0.f, 0.f);

    for (int t = 0; t < T; t++) {
        As[kq + 0][lr] = aR.x; As[kq + 1][lr] = aR.y; As[kq + 2][lr] = aR.z; As[kq + 3][lr] = aR.w;
        Bs[kq + 0][lr] = bR.x; Bs[kq + 1][lr] = bR.y; Bs[kq + 2][lr] = bR.z; Bs[kq + 3][lr] = bR.w;
        __syncthreads();
        if (t + 1 < T) {
            aR = *(const float4*)(aptr + (t + 1) * 8);
            bR = bok ? *(const float4*)(bptr + (t + 1) * 8) : make_float4(0.f, 0.f, 0.f, 0.f);
        }
#pragma unroll
        for (int k = 0; k < 8; k++) {
            float4 a0 = *(const float4*)&As[k][ty * 4];
            float4 a1 = *(const float4*)&As[k][64 + ty * 4];
            ulonglong2 bp01 = *(const ulonglong2*)&Bs[k][tx * 4];
            ulonglong2 bp23 = *(const ulonglong2*)&Bs[k][64 + tx * 4];
            unsigned long long aa[8];
            aa[0] = splat2(a0.x); aa[1] = splat2(a0.y); aa[2] = splat2(a0.z); aa[3] = splat2(a0.w);
            aa[4] = splat2(a1.x); aa[5] = splat2(a1.y); aa[6] = splat2(a1.z); aa[7] = splat2(a1.w);
#pragma unroll
            for (int i = 0; i < 8; i++) {
                fma2(acc[i][0], aa[i], bp01.x);
                fma2(acc[i][1], aa[i], bp01.y);
                fma2(acc[i][2], aa[i], bp23.x);
                fma2(acc[i][3], aa[i], bp23.y);
            }
        }
        __syncthreads();
    }

#pragma unroll
    for (int i = 0; i < 8; i++) {
        int row = m0 + ((i < 4) ? (ty * 4 + i) : (64 + ty * 4 + (i - 4)));
#pragma unroll
        for (int jh = 0; jh < 2; jh++) {
            int col = n0 + (jh ? (64 + tx * 4) : (tx * 4));
            if (col < N) {
                float2 p0 = unpack2(acc[i][jh * 2 + 0]);
                float2 p1 = unpack2(acc[i][jh * 2 + 1]);
                float v0 = p0.x, v1 = p0.y, v2 = p1.x, v3 = p1.y;
                if (bias1) { v0 += bias1[col]; v1 += bias1[col + 1]; v2 += bias1[col + 2]; v3 += bias1[col + 3]; }
                if (bias2) { v0 += bias2[col]; v1 += bias2[col + 1]; v2 += bias2[col + 2]; v3 += bias2[col + 3]; }
                if (ACT == 1) { v0 = tanhf(v0); v1 = tanhf(v1); v2 = tanhf(v2); v3 = tanhf(v3); }
                float4 v; v.x = v0; v.y = v1; v.z = v2; v.w = v3;
                *(float4*)(&C[(long)row * N + col]) = v;
            }
        }
    }
}

// ---------------- persistent LSTM layer (cooperative; all 256 steps, 1 launch) ------
// 128 CTAs (1/SM co-resident, driver-validated), 256 thr = 32 b x 8 jj.
// W_hh slice resident in smem; grid.sync() between steps (driver barrier + gpu fence).
#define HCH 132
#define PERS_SMEM ((32768 + 32 * HCH) * 4)   /* 147968 B */

__global__ void __launch_bounds__(256) lstm_layer_kernel(
    const float* __restrict__ gin,   // [S,B,4H]
    const float* __restrict__ whh,   // W_hh[l]: [4H,H]
    const float* __restrict__ fp,    // [B,S]
    const float* __restrict__ h0l,   // [B,H]
    const float* __restrict__ c0l,   // [B,H]
    float* __restrict__ x,           // [S,B,H]
    int layer)
{
    cg::grid_group grid = cg::this_grid();
    extern __shared__ float sm[];
    float* wsm = sm;                 // [1024 kk][32] = [kk][jj*4+gate]
    float* hs  = sm + 32768;         // [32 b][HCH]

    int tid = threadIdx.x;
    int j0 = blockIdx.x * 8;

    // stage W slice once: wsm[kk][jw*4+gate] = whh[gate*1024 + j0 + jw][kk]
    {
        int r = tid >> 3, t8 = tid & 7;
        int gate = r >> 3, jw = r & 7;
        int cp = jw * 4 + gate;
        const float4* wrow = (const float4*)(whh + (long)(gate * 1024 + j0 + jw) * 1024);
#pragma unroll 4
        for (int q = 0; q < 32; q++) {
            int kk4 = t8 * 32 + q;
            float4 v = wrow[kk4];
            wsm[(kk4 * 4 + 0) * 32 + cp] = v.x;
            wsm[(kk4 * 4 + 1) * 32 + cp] = v.y;
            wsm[(kk4 * 4 + 2) * 32 + cp] = v.z;
            wsm[(kk4 * 4 + 3) * 32 + cp] = v.w;
        }
    }

    int b = tid >> 3, jj = tid & 7;
    int j = j0 + jj;

    // h-chunk staging decomposition: 4 float4 per thread per 16KB chunk
    int bch[4], kof[4], so[4];
#pragma unroll
    for (int u = 0; u < 4; u++) {
        int flat = (tid + u * 256) * 4;
        bch[u] = flat >> 7; kof[u] = flat & 127;
        so[u] = bch[u] * HCH + kof[u];
    }

    float c_reg = c0l[b * Hh + j];
    __syncthreads();

    for (int s = 0; s < Ss; s++) {
        const float* hsrc = (s == 0) ? h0l : (x + (long)(s - 1) * Bb * Hh);

        // prefetch h chunk 0 (L2-coherent)
        float4 pf[4];
#pragma unroll
        for (int u = 0; u < 4; u++)
            pf[u] = ldcg4(hsrc + bch[u] * 1024 + kof[u]);

        long gb = ((long)(s * Bb + b)) * 4096 + j;
        float gi = gin[gb], gf = gin[gb + 1024], gg = gin[gb + 2048], go = gin[gb + 3072];
        float h_old = ldcg1(hsrc + b * Hh + j);
        float fpv = fp[b * Ss + s];

        unsigned long long accA0 = pack2(gi, gf), accB0 = pack2(gg, go);
        unsigned long long accA1 = 0ULL, accB1 = 0ULL;

        for (int kc = 0; kc < 8; kc++) {
#pragma unroll
            for (int u = 0; u < 4; u++) *(float4*)(hs + so[u]) = pf[u];
            __syncthreads();
            if (kc < 7) {
#pragma unroll
                for (int u = 0; u < 4; u++)
                    pf[u] = ldcg4(hsrc + bch[u] * 1024 + (kc + 1) * 128 + kof[u]);
            }
            const float* hrow = hs + b * HCH;
            const float* wb = wsm + (kc * 128) * 32 + jj * 4;
#pragma unroll 8
            for (int k4 = 0; k4 < 32; k4++) {
                float4 hv = *(const float4*)(hrow + k4 * 4);
                ulonglong2 w0 = *(const ulonglong2*)(wb + (k4 * 4 + 0) * 32);
                ulonglong2 w1 = *(const ulonglong2*)(wb + (k4 * 4 + 1) * 32);
                ulonglong2 w2 = *(const ulonglong2*)(wb + (k4 * 4 + 2) * 32);
                ulonglong2 w3 = *(const ulonglong2*)(wb + (k4 * 4 + 3) * 32);
                unsigned long long ha;
                ha = splat2(hv.x); fma2(accA0, ha, w0.x); fma2(accB0, ha, w0.y);
                ha = splat2(hv.y); fma2(accA1, ha, w1.x); fma2(accB1, ha, w1.y);
                ha = splat2(hv.z); fma2(accA0, ha, w2.x); fma2(accB0, ha, w2.y);
                ha = splat2(hv.w); fma2(accA1, ha, w3.x); fma2(accB1, ha, w3.y);
            }
            __syncthreads();
        }

        float2 a0 = unpack2(accA0), a1 = unpack2(accA1);
        float2 b0 = unpack2(accB0), b1 = unpack2(accB1);
        float i_ = sigmoidf_(a0.x + a1.x);
        float f_ = sigmoidf_(a0.y + a1.y);
        float g_ = tanhf(b0.x + b1.x);
        float o_ = sigmoidf_(b0.y + b1.y);
        float cn = f_ * c_reg + i_ * g_;
        float hn = o_ * tanhf(cn);
        float m = sigmoidf_((11.0f - fpv) * 0.25f - (float)layer);
        cn = cn * (1.0f - m) + c_reg * m;
        hn = hn * (1.0f - m) + h_old * m;
        c_reg = cn;
        x[((long)(s * Bb + b)) * Hh + j] = hn;

        // driver-managed grid barrier (full gpu-scope fence; deadlock-checked launch)
        grid.sync();
    }
}

// ---------------- launch ----------------
extern "C" void kernel_launch(void* const* d_in, const int* in_sizes, int n_in,
                              void* d_out, int out_size) {
    (void)in_sizes; (void)n_in; (void)out_size;
    const int*   src   = (const int*)  d_in[0];
    const float* fixp  = (const float*)d_in[1];
    const float* emb   = (const float*)d_in[2];
    const float* W_lin = (const float*)d_in[3];
    const float* b_lin = (const float*)d_in[4];
    const float* W_ih  = (const float*)d_in[5];
    const float* W_hh  = (const float*)d_in[6];
    const float* b_ih  = (const float*)d_in[7];
    const float* b_hh  = (const float*)d_in[8];
    const float* fc_W1 = (const float*)d_in[9];
    const float* fc_b1 = (const float*)d_in[10];
    const float* fc_W2 = (const float*)d_in[11];
    const float* fc_b2 = (const float*)d_in[12];
    const float* h0    = (const float*)d_in[13];
    const float* c0    = (const float*)d_in[14];
    float* out = (float*)d_out;

    float *fp, *inputx, *x, *gin, *hid;
    __half *ah, *al, *bw;
    cudaGetSymbolAddress((void**)&fp,     g_fp);
    cudaGetSymbolAddress((void**)&inputx, g_inputx);
    cudaGetSymbolAddress((void**)&x,      g_x);
    cudaGetSymbolAddress((void**)&gin,    g_gin);
    cudaGetSymbolAddress((void**)&hid,    g_hid);
    cudaGetSymbolAddress((void**)&ah,     g_ah);
    cudaGetSymbolAddress((void**)&al,     g_al);
    cudaGetSymbolAddress((void**)&bw,     g_bw);

    cudaFuncSetAttribute(lstm_layer_kernel,
                         cudaFuncAttributeMaxDynamicSharedMemorySize, PERS_SMEM);
    cudaFuncSetAttribute(tc_gemm_kernel,
                         cudaFuncAttributeMaxDynamicSharedMemorySize, TC_SMEM);

    const int M = Ss * Bb;   // 8192

    // 1) layer norm of fix_pred
    ln_kernel<<<Bb, 256>>>(fixp, fp);

    // 2) input projection (SGEMM, small)
    sgemm_kernel<1, 0><<<dim3(Hh / 128, M / 128), 256>>>(
        emb, W_lin, inputx, b_lin, nullptr, M, Hh, Ee, src);

    // 3) three LSTM layers
    for (int l = 0; l < Ll; l++) {
        // gated blend + fp16 split of layer input (fused)
        ew_split<<<(M * Hh) / 256, 256>>>(x, inputx, fp, ah, al, l);
        cvtB_f16<<<((long)4 * Hh * Hh + 255) / 256, 256>>>(
            W_ih + (long)l * 4 * Hh * Hh, bw, 4 * Hh, Hh, 4 * Hh);
        // gin = inp @ W_ih^T + b_ih + b_hh  (fp16 2-pass mma)
        tc_gemm_kernel<<<dim3(4 * Hh / 128, M / 128), 256, TC_SMEM>>>(
            ah, al, bw, gin,
            b_ih + (long)l * 4 * Hh, b_hh + (long)l * 4 * Hh, Hh, 4 * Hh);
        // persistent recurrence: one cooperative launch per layer
        {
            const float* ginp = gin;
            const float* whhp = W_hh + (long)l * 4 * Hh * Hh;
            const float* fpp  = fp;
            const float* h0p  = h0 + (long)l * Bb * Hh;
            const float* c0p  = c0 + (long)l * Bb * Hh;
            float* xp = x;
            int lv = l;
            void* args[] = { (void*)&ginp, (void*)&whhp, (void*)&fpp,
                             (void*)&h0p, (void*)&c0p, (void*)&xp, (void*)&lv };
            cudaLaunchCooperativeKernel((void*)lstm_layer_kernel,
                                        dim3(128, 1, 1), dim3(256, 1, 1),
                                        args, PERS_SMEM, 0);
        }
    }

    // 4) fc1 with tanh (SGEMM, small; reorders [S,B,H] -> [B,S,E])
    sgemm_kernel<2, 1><<<dim3(Ee / 128, M / 128), 256>>>(
        x, fc_W1, hid, fc_b1, nullptr, M, Ee, Hh, nullptr);

    // 5) fc2 -> logits (fp16 2-pass mma, N padded 10000 -> 10112)
    splitA_f16<<<((long)M * Ee + 255) / 256, 256>>>(hid, ah, al, (long)M * Ee);
    cvtB_f16<<<((long)NPAD_FC2 * Ee + 255) / 256, 256>>>(
        fc_W2, bw, Vv, Ee, NPAD_FC2);
    tc_gemm_kernel<<<dim3(NPAD_FC2 / 128, M / 128), 256, TC_SMEM>>>(
        ah, al, bw, out, fc_b2, nullptr, Ee, Vv);
}

// round 15
// speedup vs baseline: 4.6496x; 2.4609x over previous
#include <cuda_runtime.h>
#include <cuda_fp16.h>
#include <cooperative_groups.h>
#include <math.h>
#include <stdint.h>

namespace cg = cooperative_groups;

#define Bb 32
#define Ss 256
#define Vv 10000
#define Ee 512
#define Hh 1024
#define Ll 3

#define NPAD_FC2 10112   /* 79 * 128 */

// ---------------- scratch (static __device__ arrays; no allocation) ----------------
__device__ float g_fp[Bb * Ss];
__device__ float g_inputx[Ss * Bb * Hh];
__device__ float g_x[Ss * Bb * Hh];
__device__ float g_gin[Ss * Bb * 4 * Hh];
__device__ float g_hid[Bb * Ss * Ee];
// fp16 split scratch
__device__ __half g_ah[Ss * Bb * Hh];
__device__ __half g_al[Ss * Bb * Hh];
__device__ __half g_bw[NPAD_FC2 * Ee > 4 * Hh * Hh ? NPAD_FC2 * Ee : 4 * Hh * Hh];
// fp16 hi/lo hidden-state ping-pong for mma recurrence
__device__ __half g_hhi[2][Bb * Hh];
__device__ __half g_hlo[2][Bb * Hh];

__device__ __forceinline__ float sigmoidf_(float x) { return 1.0f / (1.0f + expf(-x)); }

// ---- packed f32x2 helpers ----
__device__ __forceinline__ unsigned long long splat2(float x) {
    unsigned long long r; asm("mov.b64 %0, {%1, %1};" : "=l"(r) : "f"(x)); return r;
}
__device__ __forceinline__ float2 unpack2(unsigned long long v) {
    float2 r; asm("mov.b64 {%0, %1}, %2;" : "=f"(r.x), "=f"(r.y) : "l"(v)); return r;
}
__device__ __forceinline__ void fma2(unsigned long long& d,
                                     unsigned long long a, unsigned long long b) {
    asm("fma.rn.f32x2 %0, %1, %2, %0;" : "+l"(d) : "l"(a), "l"(b));
}

__device__ __forceinline__ uint32_t smem_to_u32(const void* p) {
    uint32_t a;
    asm("{ .reg .u64 t; cvta.to.shared.u64 t, %1; cvt.u32.u64 %0, t; }" : "=r"(a) : "l"(p));
    return a;
}

// ---- warp-level tensor core + cp.async (baseline PTX, valid on target sm_103) ----
__device__ __forceinline__ void ldsm4(uint32_t& r0, uint32_t& r1, uint32_t& r2, uint32_t& r3,
                                      uint32_t addr) {
    asm volatile("ldmatrix.sync.aligned.m8n8.x4.shared.b16 {%0,%1,%2,%3}, [%4];"
                 : "=r"(r0), "=r"(r1), "=r"(r2), "=r"(r3) : "r"(addr));
}
__device__ __forceinline__ void mma16816h(float* d, const uint32_t* a, const uint32_t* b) {
    asm volatile(
        "mma.sync.aligned.m16n8k16.row.col.f32.f16.f16.f32 "
        "{%0,%1,%2,%3}, {%4,%5,%6,%7}, {%8,%9}, {%0,%1,%2,%3};"
        : "+f"(d[0]), "+f"(d[1]), "+f"(d[2]), "+f"(d[3])
        : "r"(a[0]), "r"(a[1]), "r"(a[2]), "r"(a[3]), "r"(b[0]), "r"(b[1]));
}
__device__ __forceinline__ void cpasync16(uint32_t s, const void* g) {
    asm volatile("cp.async.cg.shared.global [%0], [%1], 16;" :: "r"(s), "l"(g));
}
#define CP_COMMIT() asm volatile("cp.async.commit_group;" ::: "memory")
#define CP_WAIT1()  asm volatile("cp.async.wait_group 1;" ::: "memory")
#define CP_WAIT0()  asm volatile("cp.async.wait_group 0;" ::: "memory")

// ---------------- fused gated blend + fp16 hi/lo split ----------------
__global__ void ew_split(const float* __restrict__ x, const float* __restrict__ ix,
                         const float* __restrict__ fp,
                         __half* __restrict__ hi, __half* __restrict__ lo, int layer) {
    long idx = (long)blockIdx.x * 256 + threadIdx.x;
    int sb = (int)(idx >> 10);
    int b = sb & 31, s = sb >> 5;
    float alpha = (11.0f - fp[b * Ss + s]) * 0.25f - (float)layer;
    float mask = sigmoidf_(alpha);
    float gate = sigmoidf_(alpha + 1.0f) - mask;
    float xv = (layer == 0) ? 0.0f : x[idx];
    float v = xv * (1.0f - gate) + ix[idx] * gate;
    __half h = __float2half_rn(v);
    hi[idx] = h;
    lo[idx] = __float2half_rn(v - __half2float(h));
}

// ---------------- fp32 -> fp16 hi/lo split (A operand) ----------------
__global__ void splitA_f16(const float* __restrict__ in,
                           __half* __restrict__ hi, __half* __restrict__ lo, long n) {
    long idx = (long)blockIdx.x * 256 + threadIdx.x;
    if (idx >= n) return;
    float v = in[idx];
    __half h = __float2half_rn(v);
    hi[idx] = h;
    lo[idx] = __float2half_rn(v - __half2float(h));
}

// ---------------- fp32 -> fp16 single (B/weight operand, padded rows) ----------------
__global__ void cvtB_f16(const float* __restrict__ in, __half* __restrict__ out,
                         int rows, int cols, int rows_pad) {
    long idx = (long)blockIdx.x * 256 + threadIdx.x;
    long n = (long)rows_pad * cols;
    if (idx >= n) return;
    long row = idx / cols;
    out[idx] = __float2half_rn(row < rows ? in[idx] : 0.0f);
}

// ---------------- h0 -> fp16 hi/lo prep ----------------
__global__ void prep_h0(const float* __restrict__ h0l,
                        __half* __restrict__ hi, __half* __restrict__ lo) {
    int idx = blockIdx.x * 256 + threadIdx.x;
    float v = h0l[idx];
    __half h = __float2half_rn(v);
    hi[idx] = h;
    lo[idx] = __float2half_rn(v - __half2float(h));
}

// ---------------- tensor-core GEMM (R8, unchanged) ----------------
#define TCRS   80
#define TCTILE (128 * TCRS)
#define TC_SMEM (2 * 3 * TCTILE)

__global__ void __launch_bounds__(256) tc_gemm_kernel(
    const __half* __restrict__ ah, const __half* __restrict__ al,
    const __half* __restrict__ bw,
    float* __restrict__ C,
    const float* __restrict__ bias1, const float* __restrict__ bias2,
    int K, int Nout)
{
    extern __shared__ char smem[];
    uint32_t sbase = smem_to_u32(smem);

    int tid = threadIdx.x, lane = tid & 31, w = tid >> 5;
    int wm = w & 3, wn = w >> 2;
    int m0 = blockIdx.y * 128, n0 = blockIdx.x * 128;

    int srow = tid >> 1;
    int sun  = (tid & 1) * 2;
    const __half* gAh = ah + (long)(m0 + srow) * K + sun * 8;
    const __half* gAl = al + (long)(m0 + srow) * K + sun * 8;
    const __half* gB  = bw + (long)(n0 + srow) * K + sun * 8;
    int sofs = srow * TCRS + sun * 16;

    int lrow = lane & 15;
    int lcol = (lane >> 4) * 16;
    uint32_t aoff = (uint32_t)((wm * 32 + lrow) * TCRS + lcol);
    uint32_t boff = (uint32_t)(2 * TCTILE + (wn * 64 + lrow) * TCRS + lcol);

    float acc[2][8][4];
#pragma unroll
    for (int mt = 0; mt < 2; mt++)
#pragma unroll
        for (int nt = 0; nt < 8; nt++)
#pragma unroll
            for (int q = 0; q < 4; q++) acc[mt][nt][q] = 0.0f;

    int NC = K / 32;

    {
        uint32_t base = sbase;
        cpasync16(base + sofs,                  gAh);
        cpasync16(base + sofs + 16,             gAh + 8);
        cpasync16(base + TCTILE + sofs,         gAl);
        cpasync16(base + TCTILE + sofs + 16,    gAl + 8);
        cpasync16(base + 2*TCTILE + sofs,       gB);
        cpasync16(base + 2*TCTILE + sofs + 16,  gB + 8);
        CP_COMMIT();
    }

    for (int kc = 0; kc < NC; kc++) {
        int st = kc & 1;
        if (kc + 1 < NC) {
            uint32_t base = sbase + ((kc + 1) & 1) * (3 * TCTILE);
            long o = (long)(kc + 1) * 32;
            cpasync16(base + sofs,                  gAh + o);
            cpasync16(base + sofs + 16,             gAh + o + 8);
            cpasync16(base + TCTILE + sofs,         gAl + o);
            cpasync16(base + TCTILE + sofs + 16,    gAl + o + 8);
            cpasync16(base + 2*TCTILE + sofs,       gB + o);
            cpasync16(base + 2*TCTILE + sofs + 16,  gB + o + 8);
            CP_COMMIT();
            CP_WAIT1();
        } else {
            CP_WAIT0();
        }
        __syncthreads();

        uint32_t stb = sbase + st * (3 * TCTILE);
#pragma unroll
        for (int k16 = 0; k16 < 2; k16++) {
            uint32_t AH[2][4], AL[2][4];
#pragma unroll
            for (int mt = 0; mt < 2; mt++) {
                uint32_t a0 = stb + aoff + mt * (16 * TCRS) + k16 * 32;
                ldsm4(AH[mt][0], AH[mt][1], AH[mt][2], AH[mt][3], a0);
                ldsm4(AL[mt][0], AL[mt][1], AL[mt][2], AL[mt][3], a0 + TCTILE);
            }
            uint32_t Bf[8][2];
#pragma unroll
            for (int np = 0; np < 4; np++) {
                uint32_t t0, t1, t2, t3;
                uint32_t b0 = stb + boff + np * (16 * TCRS) + k16 * 32;
                ldsm4(t0, t1, t2, t3, b0);
                Bf[np*2][0] = t0; Bf[np*2][1] = t2;
                Bf[np*2+1][0] = t1; Bf[np*2+1][1] = t3;
            }
#pragma unroll
            for (int mt = 0; mt < 2; mt++)
#pragma unroll
                for (int nt = 0; nt < 8; nt++)
                    mma16816h(acc[mt][nt], AH[mt], Bf[nt]);
#pragma unroll
            for (int mt = 0; mt < 2; mt++)
#pragma unroll
                for (int nt = 0; nt < 8; nt++)
                    mma16816h(acc[mt][nt], AL[mt], Bf[nt]);
        }
        __syncthreads();
    }

    int g = lane >> 2, tq = lane & 3;
#pragma unroll
    for (int mt = 0; mt < 2; mt++) {
        int row0 = m0 + wm * 32 + mt * 16 + g;
#pragma unroll
        for (int nt = 0; nt < 8; nt++) {
            int col = n0 + wn * 64 + nt * 8 + tq * 2;
            if (col < Nout) {
                float b1v0 = bias1 ? bias1[col]     : 0.0f;
                float b1v1 = bias1 ? bias1[col + 1] : 0.0f;
                if (bias2) { b1v0 += bias2[col]; b1v1 += bias2[col + 1]; }
                float2 v01; v01.x = acc[mt][nt][0] + b1v0; v01.y = acc[mt][nt][1] + b1v1;
                float2 v23; v23.x = acc[mt][nt][2] + b1v0; v23.y = acc[mt][nt][3] + b1v1;
                *(float2*)(&C[(long)row0 * Nout + col]) = v01;
                *(float2*)(&C[(long)(row0 + 8) * Nout + col]) = v23;
            }
        }
    }
}

// ---------------- layer norm over seq dim ----------------
__global__ void ln_kernel(const float* __restrict__ fixp, float* __restrict__ fp) {
    __shared__ float red[256];
    int b = blockIdx.x, s = threadIdx.x;
    float v = fixp[b * Ss + s];
    red[s] = v;
    __syncthreads();
    for (int o = 128; o > 0; o >>= 1) { if (s < o) red[s] += red[s + o]; __syncthreads(); }
    float mu = red[0] * (1.0f / Ss);
    __syncthreads();
    float d = v - mu;
    red[s] = d * d;
    __syncthreads();
    for (int o = 128; o > 0; o >>= 1) { if (s < o) red[s] += red[s + o]; __syncthreads(); }
    float var = red[0] * (1.0f / Ss);
    float y = d * rsqrtf(var + 1e-5f);
    fp[b * Ss + s] = (y + 1.96f) / 3.92f * 12.0f;
}

// ---------------- SGEMM (R3 version) for small GEMMs ----------------
template <int MODE, int ACT>
__global__ void __launch_bounds__(256) sgemm_kernel(
    const float* __restrict__ A, const float* __restrict__ Bm, float* __restrict__ C,
    const float* __restrict__ bias1, const float* __restrict__ bias2,
    int M, int N, int K, const int* __restrict__ src)
{
    __shared__ float As[8][128];
    __shared__ float Bs[8][128];
    int tid = threadIdx.x;
    int m0 = blockIdx.y * 128, n0 = blockIdx.x * 128;

    int lr = tid >> 1;
    int kq = (tid & 1) * 4;

    int am = m0 + lr;
    long arow;
    if (MODE == 1)      { int b = am & 31;  int s = am >> 5; arow = src[b * Ss + s]; }
    else if (MODE == 2) { int s = am & 255; int b = am >> 8; arow = (long)s * Bb + b; }
    else                { arow = am; }
    const float* aptr = A + arow * (long)K + kq;

    int bn = n0 + lr;
    bool bok = (bn < N);
    const float* bptr = Bm + (long)bn * K + kq;

    int tx = tid & 15, ty = tid >> 4;

    unsigned long long acc[8][4];
#pragma unroll
    for (int i = 0; i < 8; i++)
#pragma unroll
        for (int j = 0; j < 4; j++) acc[i][j] = 0ULL;

    int T = K / 8;
    float4 aR = *(const float4*)(aptr);
    float4 bR = bok ? *(const float4*)(bptr) : make_float4(0.f, 0.f, 0.f, 0.f);

    for (int t = 0; t < T; t++) {
        As[kq + 0][lr] = aR.x; As[kq + 1][lr] = aR.y; As[kq + 2][lr] = aR.z; As[kq + 3][lr] = aR.w;
        Bs[kq + 0][lr] = bR.x; Bs[kq + 1][lr] = bR.y; Bs[kq + 2][lr] = bR.z; Bs[kq + 3][lr] = bR.w;
        __syncthreads();
        if (t + 1 < T) {
            aR = *(const float4*)(aptr + (t + 1) * 8);
            bR = bok ? *(const float4*)(bptr + (t + 1) * 8) : make_float4(0.f, 0.f, 0.f, 0.f);
        }
#pragma unroll
        for (int k = 0; k < 8; k++) {
            float4 a0 = *(const float4*)&As[k][ty * 4];
            float4 a1 = *(const float4*)&As[k][64 + ty * 4];
            ulonglong2 bp01 = *(const ulonglong2*)&Bs[k][tx * 4];
            ulonglong2 bp23 = *(const ulonglong2*)&Bs[k][64 + tx * 4];
            unsigned long long aa[8];
            aa[0] = splat2(a0.x); aa[1] = splat2(a0.y); aa[2] = splat2(a0.z); aa[3] = splat2(a0.w);
            aa[4] = splat2(a1.x); aa[5] = splat2(a1.y); aa[6] = splat2(a1.z); aa[7] = splat2(a1.w);
#pragma unroll
            for (int i = 0; i < 8; i++) {
                fma2(acc[i][0], aa[i], bp01.x);
                fma2(acc[i][1], aa[i], bp01.y);
                fma2(acc[i][2], aa[i], bp23.x);
                fma2(acc[i][3], aa[i], bp23.y);
            }
        }
        __syncthreads();
    }

#pragma unroll
    for (int i = 0; i < 8; i++) {
        int row = m0 + ((i < 4) ? (ty * 4 + i) : (64 + ty * 4 + (i - 4)));
#pragma unroll
        for (int jh = 0; jh < 2; jh++) {
            int col = n0 + (jh ? (64 + tx * 4) : (tx * 4));
            if (col < N) {
                float2 p0 = unpack2(acc[i][jh * 2 + 0]);
                float2 p1 = unpack2(acc[i][jh * 2 + 1]);
                float v0 = p0.x, v1 = p0.y, v2 = p1.x, v3 = p1.y;
                if (bias1) { v0 += bias1[col]; v1 += bias1[col + 1]; v2 += bias1[col + 2]; v3 += bias1[col + 3]; }
                if (bias2) { v0 += bias2[col]; v1 += bias2[col + 1]; v2 += bias2[col + 2]; v3 += bias2[col + 3]; }
                if (ACT == 1) { v0 = tanhf(v0); v1 = tanhf(v1); v2 = tanhf(v2); v3 = tanhf(v3); }
                float4 v; v.x = v0; v.y = v1; v.z = v2; v.w = v3;
                *(float4*)(&C[(long)row * N + col]) = v;
            }
        }
    }
}

// ---------------- persistent LSTM layer with mma.sync recurrence --------------------
// 128 CTAs cooperative (1/SM). Per CTA: 32(m batch) x 32(n = 4 gates x 8 j) x 1024(k).
// Warp w: mt=w&1 (m16), nq=(w>>1)&1 (n16), kh=w>>2 (K half of 512).
// Cross-warp K-reduction via scr[2][32][34]. grid.sync per step.
// smem: W 66048 | h-hi 66048 | h-lo 66048 | scr 2*32*34*4=8704  -> 206848 B
#define MROW 2064                    /* bytes per smem row (1024 fp16 + 8 pad) */
#define MMA_SMEM (3 * 32 * MROW + 2 * 32 * 34 * 4)

__global__ void __launch_bounds__(256) lstm_layer_mma(
    const float* __restrict__ gin,   // [S,B,4H]
    const float* __restrict__ fp,    // [B,S]
    const float* __restrict__ c0l,   // [B,H]
    float* __restrict__ x,           // [S,B,H]
    const __half* __restrict__ wh16, // W_hh fp16 [4H,H]
    int layer)
{
    cg::grid_group grid = cg::this_grid();
    extern __shared__ __half smh[];
    uint32_t sb = smem_to_u32(smh);
    const uint32_t wU  = sb;
    const uint32_t hiU = sb + 32 * MROW;
    const uint32_t loU = sb + 64 * MROW;
    float* scr = (float*)((char*)smh + 96 * MROW);  // [2][32][34]
    __half* hiS = smh + 32 * (MROW / 2);   // half-indexed views (row stride 1032 halfs)
    __half* loS = smh + 64 * (MROW / 2);

    int tid = threadIdx.x;
    int j0 = blockIdx.x * 8;
    int w = tid >> 5, lane = tid & 31;
    int mt = w & 1, nq = (w >> 1) & 1, kh = w >> 2;   // kh in 0..1
    int lrow = lane & 15, lcol = (lane >> 4) * 16;
    int g = lane >> 2, tq = lane & 3;

    // stage W slice fp16 once: smem row n = gate*8+jj  <-  global row gate*1024 + j0 + jj
    for (int i = tid; i < 32 * 128; i += 256) {
        int row = i >> 7, c16 = i & 127;
        int grow = (row >> 3) * 1024 + j0 + (row & 7);
        *(uint4*)((char*)smh + row * MROW + c16 * 16) =
            *(const uint4*)(wh16 + (long)grow * 1024 + c16 * 8);
    }

    int b = tid >> 3, jj = tid & 7;
    int j = j0 + jj;
    float c_reg = c0l[b * Hh + j];
    __syncthreads();

    // fragment base addresses (kh selects K half: 512 halfs = 1024 bytes)
    uint32_t aHi = hiU + (mt * 16 + lrow) * MROW + lcol + kh * 1024;
    uint32_t aLo = loU + (mt * 16 + lrow) * MROW + lcol + kh * 1024;
    uint32_t bWa = wU  + (nq * 16 + lrow) * MROW + lcol + kh * 1024;

    for (int s = 0; s < Ss; s++) {
        int rp = s & 1;
        const __half* srcHi = g_hhi[rp];
        const __half* srcLo = g_hlo[rp];
        // stage h hi/lo tiles [32 b][1024 k] via cp.async
#pragma unroll
        for (int i = 0; i < 16; i++) {
            int flat = tid + i * 256;
            int row = flat >> 7, c16 = flat & 127;
            cpasync16(hiU + row * MROW + c16 * 16, srcHi + row * 1024 + c16 * 8);
            cpasync16(loU + row * MROW + c16 * 16, srcLo + row * 1024 + c16 * 8);
        }
        CP_COMMIT(); CP_WAIT0();
        __syncthreads();

        float ac0[4] = {0, 0, 0, 0}, ac1[4] = {0, 0, 0, 0};
#pragma unroll 8
        for (int k16 = 0; k16 < 32; k16++) {
            uint32_t AH[4], AL[4], t0, t1, t2, t3, B0[2], B1[2];
            ldsm4(AH[0], AH[1], AH[2], AH[3], aHi + k16 * 32);
            ldsm4(AL[0], AL[1], AL[2], AL[3], aLo + k16 * 32);
            ldsm4(t0, t1, t2, t3, bWa + k16 * 32);
            B0[0] = t0; B0[1] = t2; B1[0] = t1; B1[1] = t3;
            mma16816h(ac0, AH, B0);
            mma16816h(ac1, AH, B1);
            mma16816h(ac0, AL, B0);
            mma16816h(ac1, AL, B1);
        }
        // relay fragments: scr[kh][m=32][n=32 (+2 pad)], n = gate*8+jj layout
        {
            float* sc = scr + kh * (32 * 34);
            int row0 = mt * 16 + g;                 // 0..23, +8 -> max 31
            int n0 = nq * 16 + tq * 2;              // 0..22
            int n1 = n0 + 8;                        // 8..30
            sc[row0 * 34 + n0]           = ac0[0];
            sc[row0 * 34 + n0 + 1]       = ac0[1];
            sc[(row0 + 8) * 34 + n0]     = ac0[2];
            sc[(row0 + 8) * 34 + n0 + 1] = ac0[3];
            sc[row0 * 34 + n1]           = ac1[0];
            sc[row0 * 34 + n1 + 1]       = ac1[1];
            sc[(row0 + 8) * 34 + n1]     = ac1[2];
            sc[(row0 + 8) * 34 + n1 + 1] = ac1[3];
        }
        __syncthreads();

        // pointwise gates + adaptive blend (thread = (b, jj)); sum the two K halves
        long gb = ((long)(s * Bb + b)) * 4096 + j;
        float gi_ = scr[b * 34 + jj]      + scr[32 * 34 + b * 34 + jj]      + gin[gb];
        float gf_ = scr[b * 34 + 8 + jj]  + scr[32 * 34 + b * 34 + 8 + jj]  + gin[gb + 1024];
        float gg_ = scr[b * 34 + 16 + jj] + scr[32 * 34 + b * 34 + 16 + jj] + gin[gb + 2048];
        float go_ = scr[b * 34 + 24 + jj] + scr[32 * 34 + b * 34 + 24 + jj] + gin[gb + 3072];
        float h_old = __half2float(hiS[b * (MROW / 2) + j]) +
                      __half2float(loS[b * (MROW / 2) + j]);
        float fpv = fp[b * Ss + s];
        float i_ = sigmoidf_(gi_);
        float f_ = sigmoidf_(gf_);
        float gg = tanhf(gg_);
        float o_ = sigmoidf_(go_);
        float cn = f_ * c_reg + i_ * gg;
        float hn = o_ * tanhf(cn);
        float m = sigmoidf_((11.0f - fpv) * 0.25f - (float)layer);
        cn = cn * (1.0f - m) + c_reg * m;
        hn = hn * (1.0f - m) + h_old * m;
        c_reg = cn;
        x[((long)(s * Bb + b)) * Hh + j] = hn;
        __half hh = __float2half_rn(hn);
        g_hhi[rp ^ 1][b * 1024 + j] = hh;
        g_hlo[rp ^ 1][b * 1024 + j] = __float2half_rn(hn - __half2float(hh));

        grid.sync();
    }
}

// ---------------- launch ----------------
extern "C" void kernel_launch(void* const* d_in, const int* in_sizes, int n_in,
                              void* d_out, int out_size) {
    (void)in_sizes; (void)n_in; (void)out_size;
    const int*   src   = (const int*)  d_in[0];
    const float* fixp  = (const float*)d_in[1];
    const float* emb   = (const float*)d_in[2];
    const float* W_lin = (const float*)d_in[3];
    const float* b_lin = (const float*)d_in[4];
    const float* W_ih  = (const float*)d_in[5];
    const float* W_hh  = (const float*)d_in[6];
    const float* b_ih  = (const float*)d_in[7];
    const float* b_hh  = (const float*)d_in[8];
    const float* fc_W1 = (const float*)d_in[9];
    const float* fc_b1 = (const float*)d_in[10];
    const float* fc_W2 = (const float*)d_in[11];
    const float* fc_b2 = (const float*)d_in[12];
    const float* h0    = (const float*)d_in[13];
    const float* c0    = (const float*)d_in[14];
    float* out = (float*)d_out;

    float *fp, *inputx, *x, *gin, *hid;
    __half *ah, *al, *bw, *hhi, *hlo;
    cudaGetSymbolAddress((void**)&fp,     g_fp);
    cudaGetSymbolAddress((void**)&inputx, g_inputx);
    cudaGetSymbolAddress((void**)&x,      g_x);
    cudaGetSymbolAddress((void**)&gin,    g_gin);
    cudaGetSymbolAddress((void**)&hid,    g_hid);
    cudaGetSymbolAddress((void**)&ah,     g_ah);
    cudaGetSymbolAddress((void**)&al,     g_al);
    cudaGetSymbolAddress((void**)&bw,     g_bw);
    cudaGetSymbolAddress((void**)&hhi,    g_hhi);
    cudaGetSymbolAddress((void**)&hlo,    g_hlo);

    cudaFuncSetAttribute(lstm_layer_mma,
                         cudaFuncAttributeMaxDynamicSharedMemorySize, MMA_SMEM);
    cudaFuncSetAttribute(tc_gemm_kernel,
                         cudaFuncAttributeMaxDynamicSharedMemorySize, TC_SMEM);

    const int M = Ss * Bb;   // 8192

    // 1) layer norm of fix_pred
    ln_kernel<<<Bb, 256>>>(fixp, fp);

    // 2) input projection (SGEMM, small)
    sgemm_kernel<1, 0><<<dim3(Hh / 128, M / 128), 256>>>(
        emb, W_lin, inputx, b_lin, nullptr, M, Hh, Ee, src);

    // 3) three LSTM layers
    for (int l = 0; l < Ll; l++) {
        // gated blend + fp16 split of layer input (fused)
        ew_split<<<(M * Hh) / 256, 256>>>(x, inputx, fp, ah, al, l);
        cvtB_f16<<<((long)4 * Hh * Hh + 255) / 256, 256>>>(
            W_ih + (long)l * 4 * Hh * Hh, bw, 4 * Hh, Hh, 4 * Hh);
        // gin = inp @ W_ih^T + b_ih + b_hh  (fp16 2-pass mma)
        tc_gemm_kernel<<<dim3(4 * Hh / 128, M / 128), 256, TC_SMEM>>>(
            ah, al, bw, gin,
            b_ih + (long)l * 4 * Hh, b_hh + (long)l * 4 * Hh, Hh, 4 * Hh);
        // W_hh -> fp16 (reuses bw; W_ih copy no longer needed)
        cvtB_f16<<<((long)4 * Hh * Hh + 255) / 256, 256>>>(
            W_hh + (long)l * 4 * Hh * Hh, bw, 4 * Hh, Hh, 4 * Hh);
        // h0 -> fp16 hi/lo (ping-pong buffer 0)
        prep_h0<<<(Bb * Hh) / 256, 256>>>(h0 + (long)l * Bb * Hh, hhi, hlo);
        // persistent recurrence: one cooperative launch per layer
        {
            const float* ginp = gin;
            const float* fpp  = fp;
            const float* c0p  = c0 + (long)l * Bb * Hh;
            float* xp = x;
            const __half* whp = bw;
            int lv = l;
            void* args[] = { (void*)&ginp, (void*)&fpp, (void*)&c0p,
                             (void*)&xp, (void*)&whp, (void*)&lv };
            cudaLaunchCooperativeKernel((void*)lstm_layer_mma,
                                        dim3(128, 1, 1), dim3(256, 1, 1),
                                        args, MMA_SMEM, 0);
        }
    }

    // 4) fc1 with tanh (SGEMM, small; reorders [S,B,H] -> [B,S,E])
    sgemm_kernel<2, 1><<<dim3(Ee / 128, M / 128), 256>>>(
        x, fc_W1, hid, fc_b1, nullptr, M, Ee, Hh, nullptr);

    // 5) fc2 -> logits (fp16 2-pass mma, N padded 10000 -> 10112)
    splitA_f16<<<((long)M * Ee + 255) / 256, 256>>>(hid, ah, al, (long)M * Ee);
    cvtB_f16<<<((long)NPAD_FC2 * Ee + 255) / 256, 256>>>(
        fc_W2, bw, Vv, Ee, NPAD_FC2);
    tc_gemm_kernel<<<dim3(NPAD_FC2 / 128, M / 128), 256, TC_SMEM>>>(
        ah, al, bw, out, fc_b2, nullptr, Ee, Vv);
}

// round 16
// speedup vs baseline: 5.8884x; 1.2664x over previous
#include <cuda_runtime.h>
#include <cuda_fp16.h>
#include <cooperative_groups.h>
#include <math.h>
#include <stdint.h>

namespace cg = cooperative_groups;

#define Bb 32
#define Ss 256
#define Vv 10000
#define Ee 512
#define Hh 1024
#define Ll 3

#define NPAD_FC2 10112   /* 79 * 128 */

// ---------------- scratch (static __device__ arrays; no allocation) ----------------
__device__ float g_fp[Bb * Ss];
__device__ float g_inputx[Ss * Bb * Hh];
__device__ float g_x[Ss * Bb * Hh];
__device__ float g_gin[Ss * Bb * 4 * Hh];
__device__ float g_hid[Bb * Ss * Ee];
// fp16 split scratch
__device__ __half g_ah[Ss * Bb * Hh];
__device__ __half g_al[Ss * Bb * Hh];
__device__ __half g_bw[NPAD_FC2 * Ee > 4 * Hh * Hh ? NPAD_FC2 * Ee : 4 * Hh * Hh];
// fp16 hidden-state ping-pong for mma recurrence (single fp16, no lo)
__device__ __half g_hhi[2][Bb * Hh];

__device__ __forceinline__ float sigmoidf_(float x) { return 1.0f / (1.0f + expf(-x)); }

__device__ __forceinline__ uint32_t smem_to_u32(const void* p) {
    uint32_t a;
    asm("{ .reg .u64 t; cvta.to.shared.u64 t, %1; cvt.u32.u64 %0, t; }" : "=r"(a) : "l"(p));
    return a;
}

// ---- warp-level tensor core + cp.async (baseline PTX, valid on target sm_103) ----
__device__ __forceinline__ void ldsm4(uint32_t& r0, uint32_t& r1, uint32_t& r2, uint32_t& r3,
                                      uint32_t addr) {
    asm volatile("ldmatrix.sync.aligned.m8n8.x4.shared.b16 {%0,%1,%2,%3}, [%4];"
                 : "=r"(r0), "=r"(r1), "=r"(r2), "=r"(r3) : "r"(addr));
}
__device__ __forceinline__ void mma16816h(float* d, const uint32_t* a, const uint32_t* b) {
    asm volatile(
        "mma.sync.aligned.m16n8k16.row.col.f32.f16.f16.f32 "
        "{%0,%1,%2,%3}, {%4,%5,%6,%7}, {%8,%9}, {%0,%1,%2,%3};"
        : "+f"(d[0]), "+f"(d[1]), "+f"(d[2]), "+f"(d[3])
        : "r"(a[0]), "r"(a[1]), "r"(a[2]), "r"(a[3]), "r"(b[0]), "r"(b[1]));
}
__device__ __forceinline__ void cpasync16(uint32_t s, const void* g) {
    asm volatile("cp.async.cg.shared.global [%0], [%1], 16;" :: "r"(s), "l"(g));
}
#define CP_COMMIT() asm volatile("cp.async.commit_group;" ::: "memory")
#define CP_WAIT1()  asm volatile("cp.async.wait_group 1;" ::: "memory")
#define CP_WAIT0()  asm volatile("cp.async.wait_group 0;" ::: "memory")

// ---------------- fused gated blend + fp16 hi/lo split ----------------
__global__ void ew_split(const float* __restrict__ x, const float* __restrict__ ix,
                         const float* __restrict__ fp,
                         __half* __restrict__ hi, __half* __restrict__ lo, int layer) {
    long idx = (long)blockIdx.x * 256 + threadIdx.x;
    int sb = (int)(idx >> 10);
    int b = sb & 31, s = sb >> 5;
    float alpha = (11.0f - fp[b * Ss + s]) * 0.25f - (float)layer;
    float mask = sigmoidf_(alpha);
    float gate = sigmoidf_(alpha + 1.0f) - mask;
    float xv = (layer == 0) ? 0.0f : x[idx];
    float v = xv * (1.0f - gate) + ix[idx] * gate;
    __half h = __float2half_rn(v);
    hi[idx] = h;
    lo[idx] = __float2half_rn(v - __half2float(h));
}

// ---------------- fp32 -> fp16 hi/lo split (contiguous A operand) ----------------
__global__ void splitA_f16(const float* __restrict__ in,
                           __half* __restrict__ hi, __half* __restrict__ lo, long n) {
    long idx = (long)blockIdx.x * 256 + threadIdx.x;
    if (idx >= n) return;
    float v = in[idx];
    __half h = __float2half_rn(v);
    hi[idx] = h;
    lo[idx] = __float2half_rn(v - __half2float(h));
}

// ---------------- gathered/reordered fp32 -> fp16 hi/lo split -----------------------
// MODE 1: m = s*B+b, source row = src[b*S+s]  (emb gather, proj)
// MODE 2: m = b*S+s, source row = s*B+b       (x reorder, fc1)
template <int MODE, int KK>
__global__ void splitA_gather(const float* __restrict__ in, const int* __restrict__ src,
                              __half* __restrict__ hi, __half* __restrict__ lo) {
    long idx = (long)blockIdx.x * 256 + threadIdx.x;
    int m = (int)(idx / KK);
    int k = (int)(idx - (long)m * KK);
    long row;
    if (MODE == 1) { int b = m & 31;  int s = m >> 5; row = src[b * Ss + s]; }
    else           { int s = m & 255; int b = m >> 8; row = (long)s * Bb + b; }
    float v = in[row * KK + k];
    __half h = __float2half_rn(v);
    hi[idx] = h;
    lo[idx] = __float2half_rn(v - __half2float(h));
}

// ---------------- fp32 -> fp16 single (B/weight operand, padded rows) ----------------
__global__ void cvtB_f16(const float* __restrict__ in, __half* __restrict__ out,
                         int rows, int cols, int rows_pad) {
    long idx = (long)blockIdx.x * 256 + threadIdx.x;
    long n = (long)rows_pad * cols;
    if (idx >= n) return;
    long row = idx / cols;
    out[idx] = __float2half_rn(row < rows ? in[idx] : 0.0f);
}

// ---------------- h0 -> fp16 prep ----------------
__global__ void prep_h0(const float* __restrict__ h0l, __half* __restrict__ hi) {
    int idx = blockIdx.x * 256 + threadIdx.x;
    hi[idx] = __float2half_rn(h0l[idx]);
}

// ---------------- tensor-core GEMM (hi/lo A, fp16 B; optional tanh epilogue) --------
#define TCRS   80
#define TCTILE (128 * TCRS)
#define TC_SMEM (2 * 3 * TCTILE)

template <int ACT>
__global__ void __launch_bounds__(256) tc_gemm_kernel(
    const __half* __restrict__ ah, const __half* __restrict__ al,
    const __half* __restrict__ bw,
    float* __restrict__ C,
    const float* __restrict__ bias1, const float* __restrict__ bias2,
    int K, int Nout)
{
    extern __shared__ char smem[];
    uint32_t sbase = smem_to_u32(smem);

    int tid = threadIdx.x, lane = tid & 31, w = tid >> 5;
    int wm = w & 3, wn = w >> 2;
    int m0 = blockIdx.y * 128, n0 = blockIdx.x * 128;

    int srow = tid >> 1;
    int sun  = (tid & 1) * 2;
    const __half* gAh = ah + (long)(m0 + srow) * K + sun * 8;
    const __half* gAl = al + (long)(m0 + srow) * K + sun * 8;
    const __half* gB  = bw + (long)(n0 + srow) * K + sun * 8;
    int sofs = srow * TCRS + sun * 16;

    int lrow = lane & 15;
    int lcol = (lane >> 4) * 16;
    uint32_t aoff = (uint32_t)((wm * 32 + lrow) * TCRS + lcol);
    uint32_t boff = (uint32_t)(2 * TCTILE + (wn * 64 + lrow) * TCRS + lcol);

    float acc[2][8][4];
#pragma unroll
    for (int mt = 0; mt < 2; mt++)
#pragma unroll
        for (int nt = 0; nt < 8; nt++)
#pragma unroll
            for (int q = 0; q < 4; q++) acc[mt][nt][q] = 0.0f;

    int NC = K / 32;

    {
        uint32_t base = sbase;
        cpasync16(base + sofs,                  gAh);
        cpasync16(base + sofs + 16,             gAh + 8);
        cpasync16(base + TCTILE + sofs,         gAl);
        cpasync16(base + TCTILE + sofs + 16,    gAl + 8);
        cpasync16(base + 2*TCTILE + sofs,       gB);
        cpasync16(base + 2*TCTILE + sofs + 16,  gB + 8);
        CP_COMMIT();
    }

    for (int kc = 0; kc < NC; kc++) {
        int st = kc & 1;
        if (kc + 1 < NC) {
            uint32_t base = sbase + ((kc + 1) & 1) * (3 * TCTILE);
            long o = (long)(kc + 1) * 32;
            cpasync16(base + sofs,                  gAh + o);
            cpasync16(base + sofs + 16,             gAh + o + 8);
            cpasync16(base + TCTILE + sofs,         gAl + o);
            cpasync16(base + TCTILE + sofs + 16,    gAl + o + 8);
            cpasync16(base + 2*TCTILE + sofs,       gB + o);
            cpasync16(base + 2*TCTILE + sofs + 16,  gB + o + 8);
            CP_COMMIT();
            CP_WAIT1();
        } else {
            CP_WAIT0();
        }
        __syncthreads();

        uint32_t stb = sbase + st * (3 * TCTILE);
#pragma unroll
        for (int k16 = 0; k16 < 2; k16++) {
            uint32_t AH[2][4], AL[2][4];
#pragma unroll
            for (int mt = 0; mt < 2; mt++) {
                uint32_t a0 = stb + aoff + mt * (16 * TCRS) + k16 * 32;
                ldsm4(AH[mt][0], AH[mt][1], AH[mt][2], AH[mt][3], a0);
                ldsm4(AL[mt][0], AL[mt][1], AL[mt][2], AL[mt][3], a0 + TCTILE);
            }
            uint32_t Bf[8][2];
#pragma unroll
            for (int np = 0; np < 4; np++) {
                uint32_t t0, t1, t2, t3;
                uint32_t b0 = stb + boff + np * (16 * TCRS) + k16 * 32;
                ldsm4(t0, t1, t2, t3, b0);
                Bf[np*2][0] = t0; Bf[np*2][1] = t2;
                Bf[np*2+1][0] = t1; Bf[np*2+1][1] = t3;
            }
#pragma unroll
            for (int mt = 0; mt < 2; mt++)
#pragma unroll
                for (int nt = 0; nt < 8; nt++)
                    mma16816h(acc[mt][nt], AH[mt], Bf[nt]);
#pragma unroll
            for (int mt = 0; mt < 2; mt++)
#pragma unroll
                for (int nt = 0; nt < 8; nt++)
                    mma16816h(acc[mt][nt], AL[mt], Bf[nt]);
        }
        __syncthreads();
    }

    int g = lane >> 2, tq = lane & 3;
#pragma unroll
    for (int mt = 0; mt < 2; mt++) {
        int row0 = m0 + wm * 32 + mt * 16 + g;
#pragma unroll
        for (int nt = 0; nt < 8; nt++) {
            int col = n0 + wn * 64 + nt * 8 + tq * 2;
            if (col < Nout) {
                float b1v0 = bias1 ? bias1[col]     : 0.0f;
                float b1v1 = bias1 ? bias1[col + 1] : 0.0f;
                if (bias2) { b1v0 += bias2[col]; b1v1 += bias2[col + 1]; }
                float v00 = acc[mt][nt][0] + b1v0, v01 = acc[mt][nt][1] + b1v1;
                float v10 = acc[mt][nt][2] + b1v0, v11 = acc[mt][nt][3] + b1v1;
                if (ACT == 1) { v00 = tanhf(v00); v01 = tanhf(v01); v10 = tanhf(v10); v11 = tanhf(v11); }
                float2 p0; p0.x = v00; p0.y = v01;
                float2 p1; p1.x = v10; p1.y = v11;
                *(float2*)(&C[(long)row0 * Nout + col]) = p0;
                *(float2*)(&C[(long)(row0 + 8) * Nout + col]) = p1;
            }
        }
    }
}

// ---------------- layer norm over seq dim ----------------
__global__ void ln_kernel(const float* __restrict__ fixp, float* __restrict__ fp) {
    __shared__ float red[256];
    int b = blockIdx.x, s = threadIdx.x;
    float v = fixp[b * Ss + s];
    red[s] = v;
    __syncthreads();
    for (int o = 128; o > 0; o >>= 1) { if (s < o) red[s] += red[s + o]; __syncthreads(); }
    float mu = red[0] * (1.0f / Ss);
    __syncthreads();
    float d = v - mu;
    red[s] = d * d;
    __syncthreads();
    for (int o = 128; o > 0; o >>= 1) { if (s < o) red[s] += red[s + o]; __syncthreads(); }
    float var = red[0] * (1.0f / Ss);
    float y = d * rsqrtf(var + 1e-5f);
    fp[b * Ss + s] = (y + 1.96f) / 3.92f * 12.0f;
}

// ---------------- persistent LSTM layer with mma.sync recurrence --------------------
// 128 CTAs cooperative (1/SM). Per CTA: 32(m batch) x 32(n = 4 gates x 8 j) x 1024(k).
// Warp w: mt=w&1 (m16), nq=(w>>1)&1 (n16), kh=w>>2 (K half of 512).
// h single fp16 (lo dropped — quantization measured negligible through contractive gates).
// Cross-warp K-reduction via scr[2][32][34]. grid.sync per step.
// smem: W 66048 | h 66048 | scr 8704  -> 140800 B
#define MROW 2064                    /* bytes per smem row (1024 fp16 + 8 pad) */
#define MMA_SMEM (2 * 32 * MROW + 2 * 32 * 34 * 4)

__global__ void __launch_bounds__(256) lstm_layer_mma(
    const float* __restrict__ gin,   // [S,B,4H]
    const float* __restrict__ fp,    // [B,S]
    const float* __restrict__ h0l,   // [B,H]
    const float* __restrict__ c0l,   // [B,H]
    float* __restrict__ x,           // [S,B,H]
    const __half* __restrict__ wh16, // W_hh fp16 [4H,H]
    int layer)
{
    cg::grid_group grid = cg::this_grid();
    extern __shared__ __half smh[];
    uint32_t sb = smem_to_u32(smh);
    const uint32_t wU  = sb;
    const uint32_t hiU = sb + 32 * MROW;
    float* scr = (float*)((char*)smh + 64 * MROW);  // [2][32][34]

    int tid = threadIdx.x;
    int j0 = blockIdx.x * 8;
    int w = tid >> 5, lane = tid & 31;
    int mt = w & 1, nq = (w >> 1) & 1, kh = w >> 2;   // kh in 0..1
    int lrow = lane & 15, lcol = (lane >> 4) * 16;
    int g = lane >> 2, tq = lane & 3;

    // stage W slice fp16 once: smem row n = gate*8+jj  <-  global row gate*1024 + j0 + jj
    for (int i = tid; i < 32 * 128; i += 256) {
        int row = i >> 7, c16 = i & 127;
        int grow = (row >> 3) * 1024 + j0 + (row & 7);
        *(uint4*)((char*)smh + row * MROW + c16 * 16) =
            *(const uint4*)(wh16 + (long)grow * 1024 + c16 * 8);
    }

    int b = tid >> 3, jj = tid & 7;
    int j = j0 + jj;
    float c_reg = c0l[b * Hh + j];
    __syncthreads();

    // fragment base addresses (kh selects K half: 512 halfs = 1024 bytes)
    uint32_t aHi = hiU + (mt * 16 + lrow) * MROW + lcol + kh * 1024;
    uint32_t bWa = wU  + (nq * 16 + lrow) * MROW + lcol + kh * 1024;

    for (int s = 0; s < Ss; s++) {
        int rp = s & 1;
        const __half* srcHi = g_hhi[rp];
        // stage h tile [32 b][1024 k] via cp.async (64 KB)
#pragma unroll
        for (int i = 0; i < 16; i++) {
            int flat = tid + i * 256;
            int row = flat >> 7, c16 = flat & 127;
            cpasync16(hiU + row * MROW + c16 * 16, srcHi + row * 1024 + c16 * 8);
        }
        CP_COMMIT(); CP_WAIT0();
        __syncthreads();

        float ac0[4] = {0, 0, 0, 0}, ac1[4] = {0, 0, 0, 0};
#pragma unroll 8
        for (int k16 = 0; k16 < 32; k16++) {
            uint32_t AH[4], t0, t1, t2, t3, B0[2], B1[2];
            ldsm4(AH[0], AH[1], AH[2], AH[3], aHi + k16 * 32);
            ldsm4(t0, t1, t2, t3, bWa + k16 * 32);
            B0[0] = t0; B0[1] = t2; B1[0] = t1; B1[1] = t3;
            mma16816h(ac0, AH, B0);
            mma16816h(ac1, AH, B1);
        }
        // relay fragments: scr[kh][m=32][n=32 (+2 pad)], n = gate*8+jj layout
        {
            float* sc = scr + kh * (32 * 34);
            int row0 = mt * 16 + g;
            int n0 = nq * 16 + tq * 2;
            int n1 = n0 + 8;
            sc[row0 * 34 + n0]           = ac0[0];
            sc[row0 * 34 + n0 + 1]       = ac0[1];
            sc[(row0 + 8) * 34 + n0]     = ac0[2];
            sc[(row0 + 8) * 34 + n0 + 1] = ac0[3];
            sc[row0 * 34 + n1]           = ac1[0];
            sc[row0 * 34 + n1 + 1]       = ac1[1];
            sc[(row0 + 8) * 34 + n1]     = ac1[2];
            sc[(row0 + 8) * 34 + n1 + 1] = ac1[3];
        }
        __syncthreads();

        // pointwise gates + adaptive blend (thread = (b, jj)); sum the two K halves
        long gb = ((long)(s * Bb + b)) * 4096 + j;
        float gi_ = scr[b * 34 + jj]      + scr[32 * 34 + b * 34 + jj]      + gin[gb];
        float gf_ = scr[b * 34 + 8 + jj]  + scr[32 * 34 + b * 34 + 8 + jj]  + gin[gb + 1024];
        float gg_ = scr[b * 34 + 16 + jj] + scr[32 * 34 + b * 34 + 16 + jj] + gin[gb + 2048];
        float go_ = scr[b * 34 + 24 + jj] + scr[32 * 34 + b * 34 + 24 + jj] + gin[gb + 3072];
        float h_old = (s == 0) ? h0l[b * Hh + j]
                               : x[((long)((s - 1) * Bb + b)) * Hh + j];
        float fpv = fp[b * Ss + s];
        float i_ = sigmoidf_(gi_);
        float f_ = sigmoidf_(gf_);
        float gg = tanhf(gg_);
        float o_ = sigmoidf_(go_);
        float cn = f_ * c_reg + i_ * gg;
        float hn = o_ * tanhf(cn);
        float m = sigmoidf_((11.0f - fpv) * 0.25f - (float)layer);
        cn = cn * (1.0f - m) + c_reg * m;
        hn = hn * (1.0f - m) + h_old * m;
        c_reg = cn;
        x[((long)(s * Bb + b)) * Hh + j] = hn;
        g_hhi[rp ^ 1][b * 1024 + j] = __float2half_rn(hn);

        grid.sync();
    }
}

// ---------------- launch ----------------
extern "C" void kernel_launch(void* const* d_in, const int* in_sizes, int n_in,
                              void* d_out, int out_size) {
    (void)in_sizes; (void)n_in; (void)out_size;
    const int*   src   = (const int*)  d_in[0];
    const float* fixp  = (const float*)d_in[1];
    const float* emb   = (const float*)d_in[2];
    const float* W_lin = (const float*)d_in[3];
    const float* b_lin = (const float*)d_in[4];
    const float* W_ih  = (const float*)d_in[5];
    const float* W_hh  = (const float*)d_in[6];
    const float* b_ih  = (const float*)d_in[7];
    const float* b_hh  = (const float*)d_in[8];
    const float* fc_W1 = (const float*)d_in[9];
    const float* fc_b1 = (const float*)d_in[10];
    const float* fc_W2 = (const float*)d_in[11];
    const float* fc_b2 = (const float*)d_in[12];
    const float* h0    = (const float*)d_in[13];
    const float* c0    = (const float*)d_in[14];
    float* out = (float*)d_out;

    float *fp, *inputx, *x, *gin, *hid;
    __half *ah, *al, *bw, *hhi;
    cudaGetSymbolAddress((void**)&fp,     g_fp);
    cudaGetSymbolAddress((void**)&inputx, g_inputx);
    cudaGetSymbolAddress((void**)&x,      g_x);
    cudaGetSymbolAddress((void**)&gin,    g_gin);
    cudaGetSymbolAddress((void**)&hid,    g_hid);
    cudaGetSymbolAddress((void**)&ah,     g_ah);
    cudaGetSymbolAddress((void**)&al,     g_al);
    cudaGetSymbolAddress((void**)&bw,     g_bw);
    cudaGetSymbolAddress((void**)&hhi,    g_hhi);

    cudaFuncSetAttribute(lstm_layer_mma,
                         cudaFuncAttributeMaxDynamicSharedMemorySize, MMA_SMEM);
    cudaFuncSetAttribute(tc_gemm_kernel<0>,
                         cudaFuncAttributeMaxDynamicSharedMemorySize, TC_SMEM);
    cudaFuncSetAttribute(tc_gemm_kernel<1>,
                         cudaFuncAttributeMaxDynamicSharedMemorySize, TC_SMEM);

    const int M = Ss * Bb;   // 8192

    // 1) layer norm of fix_pred
    ln_kernel<<<Bb, 256>>>(fixp, fp);

    // 2) input projection via tensor cores (emb gather + hi/lo split, then tc_gemm)
    splitA_gather<1, Ee><<<((long)M * Ee) / 256, 256>>>(emb, src, ah, al);
    cvtB_f16<<<((long)Hh * Ee + 255) / 256, 256>>>(W_lin, bw, Hh, Ee, Hh);
    tc_gemm_kernel<0><<<dim3(Hh / 128, M / 128), 256, TC_SMEM>>>(
        ah, al, bw, inputx, b_lin, nullptr, Ee, Hh);

    // 3) three LSTM layers
    for (int l = 0; l < Ll; l++) {
        // gated blend + fp16 split of layer input (fused)
        ew_split<<<(M * Hh) / 256, 256>>>(x, inputx, fp, ah, al, l);
        cvtB_f16<<<((long)4 * Hh * Hh + 255) / 256, 256>>>(
            W_ih + (long)l * 4 * Hh * Hh, bw, 4 * Hh, Hh, 4 * Hh);
        // gin = inp @ W_ih^T + b_ih + b_hh  (fp16 2-pass mma)
        tc_gemm_kernel<0><<<dim3(4 * Hh / 128, M / 128), 256, TC_SMEM>>>(
            ah, al, bw, gin,
            b_ih + (long)l * 4 * Hh, b_hh + (long)l * 4 * Hh, Hh, 4 * Hh);
        // W_hh -> fp16 (reuses bw)
        cvtB_f16<<<((long)4 * Hh * Hh + 255) / 256, 256>>>(
            W_hh + (long)l * 4 * Hh * Hh, bw, 4 * Hh, Hh, 4 * Hh);
        // h0 -> fp16 (ping-pong buffer 0)
        prep_h0<<<(Bb * Hh) / 256, 256>>>(h0 + (long)l * Bb * Hh, hhi);
        // persistent recurrence: one cooperative launch per layer
        {
            const float* ginp = gin;
            const float* fpp  = fp;
            const float* h0p  = h0 + (long)l * Bb * Hh;
            const float* c0p  = c0 + (long)l * Bb * Hh;
            float* xp = x;
            const __half* whp = bw;
            int lv = l;
            void* args[] = { (void*)&ginp, (void*)&fpp, (void*)&h0p, (void*)&c0p,
                             (void*)&xp, (void*)&whp, (void*)&lv };
            cudaLaunchCooperativeKernel((void*)lstm_layer_mma,
                                        dim3(128, 1, 1), dim3(256, 1, 1),
                                        args, MMA_SMEM, 0);
        }
    }

    // 4) fc1 with tanh via tensor cores ([S,B,H] -> [B,S,E] reorder in split)
    splitA_gather<2, Hh><<<((long)M * Hh) / 256, 256>>>(x, nullptr, ah, al);
    cvtB_f16<<<((long)Ee * Hh + 255) / 256, 256>>>(fc_W1, bw, Ee, Hh, Ee);
    tc_gemm_kernel<1><<<dim3(Ee / 128, M / 128), 256, TC_SMEM>>>(
        ah, al, bw, hid, fc_b1, nullptr, Hh, Ee);

    // 5) fc2 -> logits (fp16 2-pass mma, N padded 10000 -> 10112)
    splitA_f16<<<((long)M * Ee + 255) / 256, 256>>>(hid, ah, al, (long)M * Ee);
    cvtB_f16<<<((long)NPAD_FC2 * Ee + 255) / 256, 256>>>(
        fc_W2, bw, Vv, Ee, NPAD_FC2);
    tc_gemm_kernel<0><<<dim3(NPAD_FC2 / 128, M / 128), 256, TC_SMEM>>>(
        ah, al, bw, out, fc_b2, nullptr, Ee, Vv);
}